// round 6
// baseline (speedup 1.0000x reference)
#include <cuda_runtime.h>

// Problem constants (from reference): B=32, c_len=2048, q_len=512, D=512
#define DIMD 512
#define BATCH 32
#define CLEN 2048
#define QLEN 512

#define BM 128
#define BN 128
#define BK 16

typedef unsigned long long u64;

// Scratch (device globals: allocation-free per harness rules)
__device__ float g_cf[(size_t)BATCH * CLEN * DIMD];  // c_feat  128MB
__device__ float g_qf[(size_t)BATCH * QLEN * DIMD];  // q_feat   32MB
__device__ float g_s [(size_t)BATCH * CLEN * QLEN];  // scores/probs 128MB

// ---- packed f32x2 helpers (sm_103a FFMA2 pipe) ----
__device__ __forceinline__ u64 fma2(u64 a, u64 b, u64 c) {
    u64 d;
    asm("fma.rn.f32x2 %0, %1, %2, %3;" : "=l"(d) : "l"(a), "l"(b), "l"(c));
    return d;
}
__device__ __forceinline__ u64 dup2(float a) {
    u64 d;
    unsigned int ai = __float_as_uint(a);
    asm("mov.b64 %0, {%1, %1};" : "=l"(d) : "r"(ai));
    return d;
}
__device__ __forceinline__ float2 up2(u64 v) {
    float2 r;
    asm("mov.b64 {%0, %1}, %2;" : "=f"(r.x), "=f"(r.y) : "l"(v));
    return r;
}

// C[M,512] = op(A[M,512] @ B') (+bias)(relu), batched via blockIdx.z.
// NT=true : B is [N,512] row-major (K-contiguous), C = A·Bᵀ
// NT=false: B is [512,N] row-major (N-contiguous), C = A·B
// All inner dims are 512 (lda=ldb=ldc=512). Grid: (N/128, M/128, nbatch).
template <bool NT>
__global__ void __launch_bounds__(256, 2)
gemm512(const float* __restrict__ A, const float* __restrict__ B,
        float* __restrict__ C,
        long long sA, long long sB, long long sC,
        const float* __restrict__ bias, int relu)
{
    __shared__ __align__(16) float As[BK][BM + 4];
    __shared__ __align__(16) float Bs[BK][BN + 4];

    const int tid = threadIdx.x;
    const int tx  = tid & 15;
    const int ty  = tid >> 4;
    const int tx4 = tx * 4;
    const int ty4 = ty * 4;

    const long long z = blockIdx.z;
    A += z * sA + (long long)blockIdx.y * BM * DIMD;
    C += z * sC + (long long)blockIdx.y * BM * DIMD + (long long)blockIdx.x * BN;
    if (NT) B += z * sB + (long long)blockIdx.x * BN * DIMD;
    else    B += z * sB + (long long)blockIdx.x * BN;

    // A (and NT-B) staging: thread loads float4 at (row=tid/4 [+64], kcol=(tid%4)*4)
    const int ar  = tid >> 2;        // 0..63
    const int akc = (tid & 3) * 4;   // 0,4,8,12
    // NN-B staging: thread loads float4 at (krow=tid/32 [+8], ncol=(tid%32)*4)
    const int br  = tid >> 5;        // 0..7
    const int bc4 = (tid & 31) * 4;  // 0..124

    u64 acc[8][4];
#pragma unroll
    for (int i = 0; i < 8; i++)
#pragma unroll
        for (int j = 0; j < 4; j++) acc[i][j] = 0ull;

    float4 aP0, aP1, bP0, bP1;

    // prologue: stage tile 0 into registers
    aP0 = *(const float4*)(A + (long long)ar * DIMD + akc);
    aP1 = *(const float4*)(A + (long long)(ar + 64) * DIMD + akc);
    if (NT) {
        bP0 = *(const float4*)(B + (long long)ar * DIMD + akc);
        bP1 = *(const float4*)(B + (long long)(ar + 64) * DIMD + akc);
    } else {
        bP0 = *(const float4*)(B + (long long)br * DIMD + bc4);
        bP1 = *(const float4*)(B + (long long)(br + 8) * DIMD + bc4);
    }

    const int NTILES = DIMD / BK;  // 32
    for (int kt = 0; kt < NTILES; kt++) {
        // commit staged regs to smem (A transposed to [k][m])
        As[akc + 0][ar] = aP0.x; As[akc + 1][ar] = aP0.y;
        As[akc + 2][ar] = aP0.z; As[akc + 3][ar] = aP0.w;
        As[akc + 0][ar + 64] = aP1.x; As[akc + 1][ar + 64] = aP1.y;
        As[akc + 2][ar + 64] = aP1.z; As[akc + 3][ar + 64] = aP1.w;
        if (NT) {
            Bs[akc + 0][ar] = bP0.x; Bs[akc + 1][ar] = bP0.y;
            Bs[akc + 2][ar] = bP0.z; Bs[akc + 3][ar] = bP0.w;
            Bs[akc + 0][ar + 64] = bP1.x; Bs[akc + 1][ar + 64] = bP1.y;
            Bs[akc + 2][ar + 64] = bP1.z; Bs[akc + 3][ar + 64] = bP1.w;
        } else {
            *(float4*)&Bs[br][bc4]     = bP0;
            *(float4*)&Bs[br + 8][bc4] = bP1;
        }
        __syncthreads();

        // prefetch next tile while computing this one
        if (kt + 1 < NTILES) {
            const int k0 = (kt + 1) * BK;
            aP0 = *(const float4*)(A + (long long)ar * DIMD + k0 + akc);
            aP1 = *(const float4*)(A + (long long)(ar + 64) * DIMD + k0 + akc);
            if (NT) {
                bP0 = *(const float4*)(B + (long long)ar * DIMD + k0 + akc);
                bP1 = *(const float4*)(B + (long long)(ar + 64) * DIMD + k0 + akc);
            } else {
                bP0 = *(const float4*)(B + (long long)(k0 + br) * DIMD + bc4);
                bP1 = *(const float4*)(B + (long long)(k0 + br + 8) * DIMD + bc4);
            }
        }

#pragma unroll
        for (int kk = 0; kk < BK; kk++) {
            const float4 a0 = *(const float4*)&As[kk][ty4];
            const float4 a1 = *(const float4*)&As[kk][ty4 + 64];
            const ulonglong2 b0 = *(const ulonglong2*)&Bs[kk][tx4];
            const ulonglong2 b1 = *(const ulonglong2*)&Bs[kk][tx4 + 64];
            const float av[8] = {a0.x, a0.y, a0.z, a0.w, a1.x, a1.y, a1.z, a1.w};
            const u64   bv[4] = {b0.x, b0.y, b1.x, b1.y};
#pragma unroll
            for (int i = 0; i < 8; i++) {
                const u64 ad = dup2(av[i]);
#pragma unroll
                for (int j = 0; j < 4; j++) acc[i][j] = fma2(ad, bv[j], acc[i][j]);
            }
        }
        __syncthreads();
    }

    // epilogue
    float4 bv0 = make_float4(0.f, 0.f, 0.f, 0.f);
    float4 bv1 = bv0;
    if (bias) {
        bv0 = *(const float4*)(bias + blockIdx.x * BN + tx4);
        bv1 = *(const float4*)(bias + blockIdx.x * BN + tx4 + 64);
    }
#pragma unroll
    for (int i = 0; i < 8; i++) {
        const int row = (i < 4) ? (ty4 + i) : (ty4 + 60 + i);  // +64 group
        const float2 c0 = up2(acc[i][0]);
        const float2 c1 = up2(acc[i][1]);
        const float2 c2 = up2(acc[i][2]);
        const float2 c3 = up2(acc[i][3]);
        float4 o0 = make_float4(c0.x + bv0.x, c0.y + bv0.y, c1.x + bv0.z, c1.y + bv0.w);
        float4 o1 = make_float4(c2.x + bv1.x, c2.y + bv1.y, c3.x + bv1.z, c3.y + bv1.w);
        if (relu) {
            o0.x = fmaxf(o0.x, 0.f); o0.y = fmaxf(o0.y, 0.f);
            o0.z = fmaxf(o0.z, 0.f); o0.w = fmaxf(o0.w, 0.f);
            o1.x = fmaxf(o1.x, 0.f); o1.y = fmaxf(o1.y, 0.f);
            o1.z = fmaxf(o1.z, 0.f); o1.w = fmaxf(o1.w, 0.f);
        }
        *(float4*)(C + (long long)row * DIMD + tx4)      = o0;
        *(float4*)(C + (long long)row * DIMD + tx4 + 64) = o1;
    }
}

// Row softmax over 512 elements, in place. One block (128 threads) per row.
__global__ void softmax512(float* __restrict__ S)
{
    __shared__ float red[8];
    const long long row = blockIdx.x;
    float* p = S + row * (long long)QLEN;
    const int tid  = threadIdx.x;   // 0..127
    const int lane = tid & 31;
    const int w    = tid >> 5;

    float4 v = *(float4*)(p + tid * 4);
    float m = fmaxf(fmaxf(v.x, v.y), fmaxf(v.z, v.w));
#pragma unroll
    for (int o = 16; o; o >>= 1) m = fmaxf(m, __shfl_xor_sync(0xffffffffu, m, o));
    if (lane == 0) red[w] = m;
    __syncthreads();
    m = fmaxf(fmaxf(red[0], red[1]), fmaxf(red[2], red[3]));

    v.x = __expf(v.x - m);
    v.y = __expf(v.y - m);
    v.z = __expf(v.z - m);
    v.w = __expf(v.w - m);
    float s = v.x + v.y + v.z + v.w;
#pragma unroll
    for (int o = 16; o; o >>= 1) s += __shfl_xor_sync(0xffffffffu, s, o);
    if (lane == 0) red[4 + w] = s;
    __syncthreads();
    s = red[4] + red[5] + red[6] + red[7];

    const float inv = __frcp_rn(s);
    v.x *= inv; v.y *= inv; v.z *= inv; v.w *= inv;
    *(float4*)(p + tid * 4) = v;
}

extern "C" void kernel_launch(void* const* d_in, const int* in_sizes, int n_in,
                              void* d_out, int out_size)
{
    (void)in_sizes; (void)n_in; (void)out_size;

    const float* c = (const float*)d_in[0];  // (32,2048,512)
    const float* q = (const float*)d_in[1];  // (32,512,512)
    const float* W = (const float*)d_in[2];  // (512,512) row-major (out,in)
    const float* b = (const float*)d_in[3];  // (512)
    float* out = (float*)d_out;              // (32,2048,512)

    void *pcf, *pqf, *ps;
    cudaGetSymbolAddress(&pcf, g_cf);
    cudaGetSymbolAddress(&pqf, g_qf);
    cudaGetSymbolAddress(&ps,  g_s);
    float* cf = (float*)pcf;
    float* qf = (float*)pqf;
    float* s  = (float*)ps;

    const long long sC = (long long)CLEN * DIMD;   // 2048*512
    const long long sQ = (long long)QLEN * DIMD;   // 512*512

    // 1) c_feat = relu(c @ W^T + b)   (M = 32*2048 flattened)
    gemm512<true><<<dim3(DIMD / BN, (BATCH * CLEN) / BM, 1), 256>>>(
        c, W, cf, 0, 0, 0, b, 1);
    // 2) q_feat = relu(q @ W^T + b)   (M = 32*512 flattened)
    gemm512<true><<<dim3(DIMD / BN, (BATCH * QLEN) / BM, 1), 256>>>(
        q, W, qf, 0, 0, 0, b, 1);
    // 3) S_b = c_feat_b @ q_feat_b^T  (batched NT)
    gemm512<true><<<dim3(QLEN / BN, CLEN / BM, BATCH), 256>>>(
        cf, qf, s, sC, sQ, sC, nullptr, 0);
    // 4) row softmax over q_len
    softmax512<<<BATCH * CLEN, 128>>>(s);
    // 5) out_b = P_b @ q_b            (batched NN)
    gemm512<false><<<dim3(DIMD / BN, CLEN / BM, BATCH), 256>>>(
        s, q, out, sC, sQ, sC, nullptr, 0);
}

// round 8
// speedup vs baseline: 1.3502x; 1.3502x over previous
#include <cuda_runtime.h>
#include <cuda_bf16.h>
#include <cstdint>

// Problem constants: B=32, c_len=2048, q_len=512, D=512
#define DIMD 512
#define BATCH 32
#define CLEN 2048
#define QLEN 512

typedef unsigned long long u64;

// ============================================================================
// Device scratch (allocation-free). Extended [hi|lo] bf16 planes:
// row-major [rows][1024], hi at cols [0,512), lo at [512,1024).
// ============================================================================
__device__ __nv_bfloat16 g_cext [(size_t)BATCH * CLEN * 1024];   // c     134MB
__device__ __nv_bfloat16 g_qext [(size_t)BATCH * QLEN * 1024];   // q (A)  34MB
__device__ __nv_bfloat16 g_qtext[(size_t)BATCH * DIMD * 1024];   // q^T(B) 34MB
__device__ __nv_bfloat16 g_wext [(size_t)DIMD * 1024];           // W       1MB
__device__ __nv_bfloat16 g_cfext[(size_t)BATCH * CLEN * 1024];   // c_feat 134MB
__device__ __nv_bfloat16 g_qfext[(size_t)BATCH * QLEN * 1024];   // q_feat  34MB
__device__ __nv_bfloat16 g_pext [(size_t)BATCH * CLEN * 1024];   // probs  134MB
__device__ float         g_s    [(size_t)BATCH * CLEN * QLEN];   // scores 128MB

// ============================================================================
// Baseline-PTX tensor-core helpers (sm_80+ features; compile on plain sm_103)
// ============================================================================
__device__ __forceinline__ uint32_t smem_to_u32(const void* smem_ptr) {
    uint32_t addr;
    asm("{ .reg .u64 tmp; cvta.to.shared.u64 tmp, %1; cvt.u32.u64 %0, tmp; }"
        : "=r"(addr) : "l"(smem_ptr));
    return addr;
}
__device__ __forceinline__ void ldsm4(uint32_t* r, uint32_t addr) {
    asm volatile("ldmatrix.sync.aligned.m8n8.x4.shared.b16 {%0,%1,%2,%3}, [%4];"
        : "=r"(r[0]), "=r"(r[1]), "=r"(r[2]), "=r"(r[3]) : "r"(addr));
}
__device__ __forceinline__ void mma_bf16(float* d, const uint32_t* a,
                                         uint32_t b0, uint32_t b1) {
    asm volatile(
        "mma.sync.aligned.m16n8k16.row.col.f32.bf16.bf16.f32 "
        "{%0,%1,%2,%3}, {%4,%5,%6,%7}, {%8,%9}, {%0,%1,%2,%3};"
        : "+f"(d[0]), "+f"(d[1]), "+f"(d[2]), "+f"(d[3])
        : "r"(a[0]), "r"(a[1]), "r"(a[2]), "r"(a[3]), "r"(b0), "r"(b1));
}

// ---- hi/lo split helpers ----
__device__ __forceinline__ void split2(float x, __nv_bfloat16& h, __nv_bfloat16& l) {
    h = __float2bfloat16_rn(x);
    l = __float2bfloat16_rn(x - __bfloat162float(h));
}
__device__ __forceinline__ void split4_store(float4 v, __nv_bfloat16* dst) {
    __nv_bfloat16 h0, h1, h2, h3, l0, l1, l2, l3;
    split2(v.x, h0, l0); split2(v.y, h1, l1);
    split2(v.z, h2, l2); split2(v.w, h3, l3);
    ushort4 hs, ls;
    hs.x = __bfloat16_as_ushort(h0); hs.y = __bfloat16_as_ushort(h1);
    hs.z = __bfloat16_as_ushort(h2); hs.w = __bfloat16_as_ushort(h3);
    ls.x = __bfloat16_as_ushort(l0); ls.y = __bfloat16_as_ushort(l1);
    ls.z = __bfloat16_as_ushort(l2); ls.w = __bfloat16_as_ushort(l3);
    *(ushort4*)dst = hs;
    *(ushort4*)(dst + 512) = ls;
}
__device__ __forceinline__ void split2_store(float a, float b, __nv_bfloat16* dst) {
    __nv_bfloat16 h0, h1, l0, l1;
    split2(a, h0, l0); split2(b, h1, l1);
    ushort2 hs, ls;
    hs.x = __bfloat16_as_ushort(h0); hs.y = __bfloat16_as_ushort(h1);
    ls.x = __bfloat16_as_ushort(l0); ls.y = __bfloat16_as_ushort(l1);
    *(ushort2*)dst = hs;
    *(ushort2*)(dst + 512) = ls;
}

// ============================================================================
// Split kernels: fp32 [rows][512] -> bf16 ext [rows][1024] (hi|lo)
// ============================================================================
__global__ void split_ext(const float* __restrict__ src,
                          __nv_bfloat16* __restrict__ dst, long long n4)
{
    long long i = (long long)blockIdx.x * blockDim.x + threadIdx.x;
    if (i >= n4) return;
    long long e = i * 4;
    long long row = e >> 9;
    int col = (int)(e & 511);
    float4 v = *(const float4*)(src + e);
    split4_store(v, dst + row * 1024 + col);
}

// q[b][p][d] -> qT_ext[(b*512+d)][p(hi)|512+p(lo)]
__global__ void transpose_split(const float* __restrict__ q,
                                __nv_bfloat16* __restrict__ dst)
{
    __shared__ float t[32][33];
    const int b = blockIdx.z, d0 = blockIdx.x * 32, p0 = blockIdx.y * 32;
    const float* qb = q + ((long long)b * QLEN + p0) * DIMD + d0;
    for (int i = threadIdx.y; i < 32; i += 8)
        t[i][threadIdx.x] = qb[(long long)i * DIMD + threadIdx.x];
    __syncthreads();
    for (int i = threadIdx.y; i < 32; i += 8) {
        float v = t[threadIdx.x][i];
        __nv_bfloat16 h, l;
        split2(v, h, l);
        __nv_bfloat16* dp = dst + ((long long)b * DIMD + d0 + i) * 1024 + p0 + threadIdx.x;
        dp[0] = h;
        dp[512] = l;
    }
}

// ============================================================================
// Split-precision bf16 mma.sync GEMM.
// D[128,128] = A[128,512]·B[128,512]^T via 3 terms Ah·Bh + Al·Bh + Ah·Bl,
// fp32 accumulation, planes fused per K-chunk (one data pass).
// Block: 256 thr = 8 warps (2 M x 4 N), warp tile 64x32, K-chunk 16.
// EXT=true : C = relu(D + bias) -> bf16 [hi|lo] ext (pitch 1024)
// EXT=false: C = D -> fp32, pitch cPitch
// ============================================================================
// smem per stage: Ah|Al|Bh|Bl, each 128 rows x 16 k x 2B = 4KB -> 16KB; x2 buf
#define GSTAGE 16384
#define GEMM_DSMEM (2 * GSTAGE)

// swizzled 16B-chunk offset within a 4KB plane: row 0..127, c 0..1
__device__ __forceinline__ uint32_t swz(int row, int c) {
    return (uint32_t)(row * 32 + ((c ^ ((row >> 2) & 1)) << 4));
}

template <bool EXT>
__global__ void __launch_bounds__(256, 1)
gemm_mma(const __nv_bfloat16* __restrict__ A, const __nv_bfloat16* __restrict__ B,
         float* __restrict__ C, __nv_bfloat16* __restrict__ CE,
         const float* __restrict__ bias,
         long long aZ, long long bZ, long long cZ, int cPitch)
{
    extern __shared__ char dsm[];
    const uint32_t smem0 = smem_to_u32(dsm);

    const int tid = threadIdx.x;
    const int lane = tid & 31;
    const int wid = tid >> 5;
    const int wm = wid & 1;       // 0..1  (M)
    const int wn = wid >> 1;      // 0..3  (N)

    const long long z = blockIdx.z;
    const __nv_bfloat16* Ab = A + (z * aZ + (long long)blockIdx.y * 128) * 1024;
    const __nv_bfloat16* Bb = B + (z * bZ + (long long)blockIdx.x * 128) * 1024;

    // gmem staging role: thread -> (row, 16B chunk)
    const int grow = tid >> 1;          // 0..127
    const int gc   = tid & 1;           // 0..1
    const __nv_bfloat16* gA = Ab + (long long)grow * 1024 + gc * 8;
    const __nv_bfloat16* gB = Bb + (long long)grow * 1024 + gc * 8;
    const uint32_t gsw = swz(grow, gc);

    // ldmatrix addresses (per-lane), offsets within a 4KB plane
    uint32_t offA[4], offB[2];
#pragma unroll
    for (int mf = 0; mf < 4; mf++)
        offA[mf] = swz(wm * 64 + mf * 16 + (lane & 15), lane >> 4);
#pragma unroll
    for (int nf = 0; nf < 2; nf++)
        offB[nf] = swz(wn * 32 + nf * 16 + (lane & 15), lane >> 4);

    float acc[4][4][4];
#pragma unroll
    for (int i = 0; i < 4; i++)
#pragma unroll
        for (int j = 0; j < 4; j++)
#pragma unroll
            for (int k = 0; k < 4; k++) acc[i][j][k] = 0.f;

    // prologue prefetch (k0 = 0)
    float4 pAh = *(const float4*)(gA);
    float4 pAl = *(const float4*)(gA + 512);
    float4 pBh = *(const float4*)(gB);
    float4 pBl = *(const float4*)(gB + 512);

#pragma unroll 1
    for (int kt = 0; kt < 32; kt++) {
        const uint32_t stage = smem0 + (kt & 1) * GSTAGE;
        // commit staged chunks: planes Ah|Al|Bh|Bl at +0,4K,8K,12K
        {
            char* sp = dsm + (kt & 1) * GSTAGE + gsw;
            *(float4*)(sp)         = pAh;
            *(float4*)(sp + 4096)  = pAl;
            *(float4*)(sp + 8192)  = pBh;
            *(float4*)(sp + 12288) = pBl;
        }
        __syncthreads();

        if (kt + 1 < 32) {
            const int k0 = (kt + 1) * 16;
            pAh = *(const float4*)(gA + k0);
            pAl = *(const float4*)(gA + 512 + k0);
            pBh = *(const float4*)(gB + k0);
            pBl = *(const float4*)(gB + 512 + k0);
        }

        // B fragments: [nf16][4 regs]; frag(n0-7)={r0,r2}, frag(n8-15)={r1,r3}
        uint32_t Bh[2][4], Bl[2][4];
#pragma unroll
        for (int nf = 0; nf < 2; nf++) {
            ldsm4(Bh[nf], stage + 8192  + offB[nf]);
            ldsm4(Bl[nf], stage + 12288 + offB[nf]);
        }
#pragma unroll
        for (int mf = 0; mf < 4; mf++) {
            uint32_t Ah[4], Al[4];
            ldsm4(Ah, stage +        offA[mf]);
            ldsm4(Al, stage + 4096 + offA[mf]);
#pragma unroll
            for (int n8 = 0; n8 < 4; n8++) {
                const int nf = n8 >> 1, h = n8 & 1;
                const uint32_t b0h = Bh[nf][h], b1h = Bh[nf][h + 2];
                const uint32_t b0l = Bl[nf][h], b1l = Bl[nf][h + 2];
                mma_bf16(acc[mf][n8], Ah, b0h, b1h);
                mma_bf16(acc[mf][n8], Al, b0h, b1h);
                mma_bf16(acc[mf][n8], Ah, b0l, b1l);
            }
        }
        __syncthreads();
    }

    // ---- epilogue: acc -> gmem (fragment layout m16n8 f32) ----
    const int rbase = blockIdx.y * 128 + wm * 64 + (lane >> 2);
    const int cbase = blockIdx.x * 128 + wn * 32 + (lane & 3) * 2;

    if (EXT) {
        __nv_bfloat16* CEb = CE + (z * cZ) * 1024;
#pragma unroll
        for (int mf = 0; mf < 4; mf++) {
#pragma unroll
            for (int n8 = 0; n8 < 4; n8++) {
                const int col = cbase + n8 * 8;
                float b0 = bias ? bias[col]     : 0.f;
                float b1 = bias ? bias[col + 1] : 0.f;
                const float* a = acc[mf][n8];
                const int r0 = rbase + mf * 16;
                float v0 = fmaxf(a[0] + b0, 0.f), v1 = fmaxf(a[1] + b1, 0.f);
                float v2 = fmaxf(a[2] + b0, 0.f), v3 = fmaxf(a[3] + b1, 0.f);
                split2_store(v0, v1, CEb + (long long)r0 * 1024 + col);
                split2_store(v2, v3, CEb + (long long)(r0 + 8) * 1024 + col);
            }
        }
    } else {
        float* Cb = C + z * cZ;
#pragma unroll
        for (int mf = 0; mf < 4; mf++) {
#pragma unroll
            for (int n8 = 0; n8 < 4; n8++) {
                const int col = cbase + n8 * 8;
                const float* a = acc[mf][n8];
                const int r0 = rbase + mf * 16;
                *(float2*)(Cb + (long long)r0 * cPitch + col) =
                    make_float2(a[0], a[1]);
                *(float2*)(Cb + (long long)(r0 + 8) * cPitch + col) =
                    make_float2(a[2], a[3]);
            }
        }
    }
}

// ============================================================================
// Row softmax over 512, fp32 in -> bf16 [hi|lo] ext out. 128 threads/row.
// ============================================================================
__global__ void softmax_ext(const float* __restrict__ S,
                            __nv_bfloat16* __restrict__ P)
{
    __shared__ float red[8];
    const long long row = blockIdx.x;
    const float* p = S + row * (long long)QLEN;
    const int tid = threadIdx.x, lane = tid & 31, w = tid >> 5;

    float4 v = *(const float4*)(p + tid * 4);
    float m = fmaxf(fmaxf(v.x, v.y), fmaxf(v.z, v.w));
#pragma unroll
    for (int o = 16; o; o >>= 1) m = fmaxf(m, __shfl_xor_sync(0xffffffffu, m, o));
    if (lane == 0) red[w] = m;
    __syncthreads();
    m = fmaxf(fmaxf(red[0], red[1]), fmaxf(red[2], red[3]));

    v.x = __expf(v.x - m);
    v.y = __expf(v.y - m);
    v.z = __expf(v.z - m);
    v.w = __expf(v.w - m);
    float s = v.x + v.y + v.z + v.w;
#pragma unroll
    for (int o = 16; o; o >>= 1) s += __shfl_xor_sync(0xffffffffu, s, o);
    if (lane == 0) red[4 + w] = s;
    __syncthreads();
    s = red[4] + red[5] + red[6] + red[7];

    const float inv = __frcp_rn(s);
    v.x *= inv; v.y *= inv; v.z *= inv; v.w *= inv;
    split4_store(v, P + row * 1024 + tid * 4);
}

// ============================================================================
// Host launcher
// ============================================================================
extern "C" void kernel_launch(void* const* d_in, const int* in_sizes, int n_in,
                              void* d_out, int out_size)
{
    (void)in_sizes; (void)n_in; (void)out_size;

    const float* c = (const float*)d_in[0];  // (32,2048,512)
    const float* q = (const float*)d_in[1];  // (32,512,512)
    const float* W = (const float*)d_in[2];  // (512,512) (out,in)
    const float* b = (const float*)d_in[3];  // (512)
    float* out = (float*)d_out;              // (32,2048,512)

    void *pce, *pqe, *pqt, *pwe, *pcf, *pqf, *ppe, *ps;
    cudaGetSymbolAddress(&pce, g_cext);
    cudaGetSymbolAddress(&pqe, g_qext);
    cudaGetSymbolAddress(&pqt, g_qtext);
    cudaGetSymbolAddress(&pwe, g_wext);
    cudaGetSymbolAddress(&pcf, g_cfext);
    cudaGetSymbolAddress(&pqf, g_qfext);
    cudaGetSymbolAddress(&ppe, g_pext);
    cudaGetSymbolAddress(&ps,  g_s);
    __nv_bfloat16* cext  = (__nv_bfloat16*)pce;
    __nv_bfloat16* qext  = (__nv_bfloat16*)pqe;
    __nv_bfloat16* qtext = (__nv_bfloat16*)pqt;
    __nv_bfloat16* wext  = (__nv_bfloat16*)pwe;
    __nv_bfloat16* cfext = (__nv_bfloat16*)pcf;
    __nv_bfloat16* qfext = (__nv_bfloat16*)pqf;
    __nv_bfloat16* pext  = (__nv_bfloat16*)ppe;
    float* sbuf = (float*)ps;

    cudaFuncSetAttribute(gemm_mma<true>,
                         cudaFuncAttributeMaxDynamicSharedMemorySize, GEMM_DSMEM);
    cudaFuncSetAttribute(gemm_mma<false>,
                         cudaFuncAttributeMaxDynamicSharedMemorySize, GEMM_DSMEM);

    // Input splits
    {
        long long n4 = (long long)BATCH * CLEN * DIMD / 4;
        split_ext<<<(unsigned)((n4 + 255) / 256), 256>>>(c, cext, n4);
    }
    {
        long long n4 = (long long)BATCH * QLEN * DIMD / 4;
        split_ext<<<(unsigned)((n4 + 255) / 256), 256>>>(q, qext, n4);
    }
    {
        long long n4 = (long long)DIMD * DIMD / 4;
        split_ext<<<(unsigned)((n4 + 255) / 256), 256>>>(W, wext, n4);
    }
    transpose_split<<<dim3(DIMD / 32, QLEN / 32, BATCH), dim3(32, 8)>>>(q, qtext);

    // 1) c_feat = relu(c @ W^T + b) -> ext   (M=65536, N=512)
    gemm_mma<true><<<dim3(4, 512, 1), 256, GEMM_DSMEM>>>(
        cext, wext, nullptr, cfext, b, 0, 0, 0, 0);
    // 2) q_feat = relu(q @ W^T + b) -> ext   (M=16384, N=512)
    gemm_mma<true><<<dim3(4, 128, 1), 256, GEMM_DSMEM>>>(
        qext, wext, nullptr, qfext, b, 0, 0, 0, 0);
    // 3) S_b = c_feat_b @ q_feat_b^T -> fp32 (per-batch M=2048, N=512)
    gemm_mma<false><<<dim3(4, 16, 32), 256, GEMM_DSMEM>>>(
        cfext, qfext, sbuf, nullptr, nullptr,
        (long long)CLEN, (long long)QLEN, (long long)CLEN * QLEN, QLEN);
    // 4) row softmax -> probs ext
    softmax_ext<<<BATCH * CLEN, 128>>>(sbuf, pext);
    // 5) mix_b = P_b @ q_b -> fp32 out       (per-batch M=2048, N=512)
    gemm_mma<false><<<dim3(4, 16, 32), 256, GEMM_DSMEM>>>(
        pext, qtext, out, nullptr, nullptr,
        (long long)CLEN, (long long)DIMD, (long long)CLEN * DIMD, DIMD);
}

// round 13
// speedup vs baseline: 1.6029x; 1.1871x over previous
#include <cuda_runtime.h>
#include <cuda_bf16.h>
#include <cstdint>

// Problem constants: B=32, c_len=2048, q_len=512, D=512
#define DIMD 512
#define BATCH 32
#define CLEN 2048
#define QLEN 512

typedef unsigned long long u64;

// ============================================================================
// Device scratch (allocation-free). Extended [hi|lo] bf16 planes:
// row-major [rows][1024], hi at cols [0,512), lo at [512,1024).
// ============================================================================
__device__ __nv_bfloat16 g_cext [(size_t)BATCH * CLEN * 1024];   // c     134MB
__device__ __nv_bfloat16 g_qext [(size_t)BATCH * QLEN * 1024];   // q (A)  34MB
__device__ __nv_bfloat16 g_qtext[(size_t)BATCH * DIMD * 1024];   // q^T(B) 34MB
__device__ __nv_bfloat16 g_wext [(size_t)DIMD * 1024];           // W       1MB
__device__ __nv_bfloat16 g_cfext[(size_t)BATCH * CLEN * 1024];   // c_feat 134MB
__device__ __nv_bfloat16 g_qfext[(size_t)BATCH * QLEN * 1024];   // q_feat  34MB
__device__ __nv_bfloat16 g_pext [(size_t)BATCH * CLEN * 1024];   // probs  134MB
__device__ float         g_s    [(size_t)BATCH * CLEN * QLEN];   // scores 128MB

// ============================================================================
// Baseline-PTX helpers (all sm_80+ features; compile on plain sm_103)
// ============================================================================
__device__ __forceinline__ uint32_t smem_to_u32(const void* smem_ptr) {
    uint32_t addr;
    asm("{ .reg .u64 tmp; cvta.to.shared.u64 tmp, %1; cvt.u32.u64 %0, tmp; }"
        : "=r"(addr) : "l"(smem_ptr));
    return addr;
}
__device__ __forceinline__ void ldsm4(uint32_t* r, uint32_t addr) {
    asm volatile("ldmatrix.sync.aligned.m8n8.x4.shared.b16 {%0,%1,%2,%3}, [%4];"
        : "=r"(r[0]), "=r"(r[1]), "=r"(r[2]), "=r"(r[3]) : "r"(addr));
}
__device__ __forceinline__ void mma_bf16(float* d, const uint32_t* a,
                                         uint32_t b0, uint32_t b1) {
    asm volatile(
        "mma.sync.aligned.m16n8k16.row.col.f32.bf16.bf16.f32 "
        "{%0,%1,%2,%3}, {%4,%5,%6,%7}, {%8,%9}, {%0,%1,%2,%3};"
        : "+f"(d[0]), "+f"(d[1]), "+f"(d[2]), "+f"(d[3])
        : "r"(a[0]), "r"(a[1]), "r"(a[2]), "r"(a[3]), "r"(b0), "r"(b1));
}
#define CP_ASYNC16(dst, src) \
    asm volatile("cp.async.cg.shared.global [%0], [%1], 16;" \
        :: "r"(dst), "l"(src) : "memory")
#define CP_COMMIT() asm volatile("cp.async.commit_group;" ::: "memory")
#define CP_WAIT2()  asm volatile("cp.async.wait_group 2;" ::: "memory")

// ---- hi/lo split helpers ----
__device__ __forceinline__ void split2(float x, __nv_bfloat16& h, __nv_bfloat16& l) {
    h = __float2bfloat16_rn(x);
    l = __float2bfloat16_rn(x - __bfloat162float(h));
}
__device__ __forceinline__ void split4_store(float4 v, __nv_bfloat16* dst) {
    __nv_bfloat16 h0, h1, h2, h3, l0, l1, l2, l3;
    split2(v.x, h0, l0); split2(v.y, h1, l1);
    split2(v.z, h2, l2); split2(v.w, h3, l3);
    ushort4 hs, ls;
    hs.x = __bfloat16_as_ushort(h0); hs.y = __bfloat16_as_ushort(h1);
    hs.z = __bfloat16_as_ushort(h2); hs.w = __bfloat16_as_ushort(h3);
    ls.x = __bfloat16_as_ushort(l0); ls.y = __bfloat16_as_ushort(l1);
    ls.z = __bfloat16_as_ushort(l2); ls.w = __bfloat16_as_ushort(l3);
    *(ushort4*)dst = hs;
    *(ushort4*)(dst + 512) = ls;
}
__device__ __forceinline__ void split2_store(float a, float b, __nv_bfloat16* dst) {
    __nv_bfloat16 h0, h1, l0, l1;
    split2(a, h0, l0); split2(b, h1, l1);
    ushort2 hs, ls;
    hs.x = __bfloat16_as_ushort(h0); hs.y = __bfloat16_as_ushort(h1);
    ls.x = __bfloat16_as_ushort(l0); ls.y = __bfloat16_as_ushort(l1);
    *(ushort2*)dst = hs;
    *(ushort2*)(dst + 512) = ls;
}

// ============================================================================
// Split kernels: fp32 [rows][512] -> bf16 ext [rows][1024] (hi|lo)
// ============================================================================
__global__ void split_ext(const float* __restrict__ src,
                          __nv_bfloat16* __restrict__ dst, long long n4)
{
    long long i = (long long)blockIdx.x * blockDim.x + threadIdx.x;
    if (i >= n4) return;
    long long e = i * 4;
    long long row = e >> 9;
    int col = (int)(e & 511);
    float4 v = *(const float4*)(src + e);
    split4_store(v, dst + row * 1024 + col);
}

// q[b][p][d] -> qT_ext[(b*512+d)][p(hi)|512+p(lo)]
__global__ void transpose_split(const float* __restrict__ q,
                                __nv_bfloat16* __restrict__ dst)
{
    __shared__ float t[32][33];
    const int b = blockIdx.z, d0 = blockIdx.x * 32, p0 = blockIdx.y * 32;
    const float* qb = q + ((long long)b * QLEN + p0) * DIMD + d0;
    for (int i = threadIdx.y; i < 32; i += 8)
        t[i][threadIdx.x] = qb[(long long)i * DIMD + threadIdx.x];
    __syncthreads();
    for (int i = threadIdx.y; i < 32; i += 8) {
        float v = t[threadIdx.x][i];
        __nv_bfloat16 h, l;
        split2(v, h, l);
        __nv_bfloat16* dp = dst + ((long long)b * DIMD + d0 + i) * 1024 + p0 + threadIdx.x;
        dp[0] = h;
        dp[512] = l;
    }
}

// ============================================================================
// Split-precision bf16 mma.sync GEMM, 4-stage cp.async pipeline.
// D[128,128] = A[128,512]·B[128,512]^T via Ah·Bh + Al·Bh + Ah·Bl, fp32 accum.
// Block: 256 thr = 8 warps (2 M x 4 N), warp tile 64x32, K-chunk 16.
// smem stage: Ah|Al|Bh|Bl planes (4KB each) = 16KB; 4 stages = 64KB.
// EXT=true : C = relu(D + bias) -> bf16 [hi|lo] ext (pitch 1024)
// EXT=false: C = D -> fp32, pitch cPitch
// ============================================================================
#define GSTAGE 16384
#define GEMM_DSMEM (4 * GSTAGE)

// swizzled 16B-chunk offset within a 4KB plane: row 0..127, c 0..1
__device__ __forceinline__ uint32_t swz(int row, int c) {
    return (uint32_t)(row * 32 + ((c ^ ((row >> 2) & 1)) << 4));
}

template <bool EXT>
__global__ void __launch_bounds__(256)
gemm_mma(const __nv_bfloat16* __restrict__ A, const __nv_bfloat16* __restrict__ B,
         float* __restrict__ C, __nv_bfloat16* __restrict__ CE,
         const float* __restrict__ bias,
         long long aZ, long long bZ, long long cZ, int cPitch)
{
    extern __shared__ char dsm[];
    const uint32_t smem0 = smem_to_u32(dsm);

    const int tid = threadIdx.x;
    const int lane = tid & 31;
    const int wid = tid >> 5;
    const int wm = wid & 1;       // 0..1  (M)
    const int wn = wid >> 1;      // 0..3  (N)

    const long long z = blockIdx.z;
    const __nv_bfloat16* Ab = A + (z * aZ + (long long)blockIdx.y * 128) * 1024;
    const __nv_bfloat16* Bb = B + (z * bZ + (long long)blockIdx.x * 128) * 1024;

    // gmem staging role: thread -> (row, 16B chunk)
    const int grow = tid >> 1;          // 0..127
    const int gc   = tid & 1;           // 0..1
    const __nv_bfloat16* gA = Ab + (long long)grow * 1024 + gc * 8;
    const __nv_bfloat16* gB = Bb + (long long)grow * 1024 + gc * 8;
    const uint32_t gsw = swz(grow, gc);

    // ldmatrix addresses (per-lane), offsets within a 4KB plane
    uint32_t offA[4], offB[2];
#pragma unroll
    for (int mf = 0; mf < 4; mf++)
        offA[mf] = swz(wm * 64 + mf * 16 + (lane & 15), lane >> 4);
#pragma unroll
    for (int nf = 0; nf < 2; nf++)
        offB[nf] = swz(wn * 32 + nf * 16 + (lane & 15), lane >> 4);

    float acc[4][4][4];
#pragma unroll
    for (int i = 0; i < 4; i++)
#pragma unroll
        for (int j = 0; j < 4; j++)
#pragma unroll
            for (int k = 0; k < 4; k++) acc[i][j][k] = 0.f;

    // prologue: issue stages 0..2 (one commit group per stage)
#pragma unroll
    for (int s = 0; s < 3; s++) {
        const uint32_t sp = smem0 + s * GSTAGE + gsw;
        const int k0 = s * 16;
        CP_ASYNC16(sp,         (const char*)(gA + k0));
        CP_ASYNC16(sp + 4096,  (const char*)(gA + 512 + k0));
        CP_ASYNC16(sp + 8192,  (const char*)(gB + k0));
        CP_ASYNC16(sp + 12288, (const char*)(gB + 512 + k0));
        CP_COMMIT();
    }

#pragma unroll 1
    for (int kt = 0; kt < 32; kt++) {
        CP_WAIT2();                 // stage kt resident (group accounting below)
        __syncthreads();            // visible to all warps; frees slot (kt-1)&3

        // issue stage kt+3 into slot (kt+3)&3 == (kt-1)&3; commit ALWAYS so
        // groups committed before iter kt's wait == 3+kt  ->  wait_group 2
        // retires exactly through stage kt.
        if (kt + 3 < 32) {
            const uint32_t sp = smem0 + ((kt + 3) & 3) * GSTAGE + gsw;
            const int k0 = (kt + 3) * 16;
            CP_ASYNC16(sp,         (const char*)(gA + k0));
            CP_ASYNC16(sp + 4096,  (const char*)(gA + 512 + k0));
            CP_ASYNC16(sp + 8192,  (const char*)(gB + k0));
            CP_ASYNC16(sp + 12288, (const char*)(gB + 512 + k0));
        }
        CP_COMMIT();

        const uint32_t stage = smem0 + (kt & 3) * GSTAGE;

        // B fragments: [nf16][4 regs]; frag(n0-7)={r0,r2}, frag(n8-15)={r1,r3}
        uint32_t Bh[2][4], Bl[2][4];
#pragma unroll
        for (int nf = 0; nf < 2; nf++) {
            ldsm4(Bh[nf], stage + 8192  + offB[nf]);
            ldsm4(Bl[nf], stage + 12288 + offB[nf]);
        }
#pragma unroll
        for (int mf = 0; mf < 4; mf++) {
            uint32_t Ah[4], Al[4];
            ldsm4(Ah, stage +        offA[mf]);
            ldsm4(Al, stage + 4096 + offA[mf]);
#pragma unroll
            for (int n8 = 0; n8 < 4; n8++) {
                const int nf = n8 >> 1, h = n8 & 1;
                const uint32_t b0h = Bh[nf][h], b1h = Bh[nf][h + 2];
                const uint32_t b0l = Bl[nf][h], b1l = Bl[nf][h + 2];
                mma_bf16(acc[mf][n8], Ah, b0h, b1h);
                mma_bf16(acc[mf][n8], Al, b0h, b1h);
                mma_bf16(acc[mf][n8], Ah, b0l, b1l);
            }
        }
        // no trailing barrier: next iteration's syncthreads protects reuse
    }

    // ---- epilogue: acc -> gmem (fragment layout m16n8 f32) ----
    const int rbase = blockIdx.y * 128 + wm * 64 + (lane >> 2);
    const int cbase = blockIdx.x * 128 + wn * 32 + (lane & 3) * 2;

    if (EXT) {
        __nv_bfloat16* CEb = CE + (z * cZ) * 1024;
#pragma unroll
        for (int mf = 0; mf < 4; mf++) {
#pragma unroll
            for (int n8 = 0; n8 < 4; n8++) {
                const int col = cbase + n8 * 8;
                float b0 = bias ? bias[col]     : 0.f;
                float b1 = bias ? bias[col + 1] : 0.f;
                const float* a = acc[mf][n8];
                const int r0 = rbase + mf * 16;
                float v0 = fmaxf(a[0] + b0, 0.f), v1 = fmaxf(a[1] + b1, 0.f);
                float v2 = fmaxf(a[2] + b0, 0.f), v3 = fmaxf(a[3] + b1, 0.f);
                split2_store(v0, v1, CEb + (long long)r0 * 1024 + col);
                split2_store(v2, v3, CEb + (long long)(r0 + 8) * 1024 + col);
            }
        }
    } else {
        float* Cb = C + z * cZ;
#pragma unroll
        for (int mf = 0; mf < 4; mf++) {
#pragma unroll
            for (int n8 = 0; n8 < 4; n8++) {
                const int col = cbase + n8 * 8;
                const float* a = acc[mf][n8];
                const int r0 = rbase + mf * 16;
                *(float2*)(Cb + (long long)r0 * cPitch + col) =
                    make_float2(a[0], a[1]);
                *(float2*)(Cb + (long long)(r0 + 8) * cPitch + col) =
                    make_float2(a[2], a[3]);
            }
        }
    }
}

// ============================================================================
// Row softmax over 512, fp32 in -> bf16 [hi|lo] ext out. 128 threads/row.
// ============================================================================
__global__ void softmax_ext(const float* __restrict__ S,
                            __nv_bfloat16* __restrict__ P)
{
    __shared__ float red[8];
    const long long row = blockIdx.x;
    const float* p = S + row * (long long)QLEN;
    const int tid = threadIdx.x, lane = tid & 31, w = tid >> 5;

    float4 v = *(const float4*)(p + tid * 4);
    float m = fmaxf(fmaxf(v.x, v.y), fmaxf(v.z, v.w));
#pragma unroll
    for (int o = 16; o; o >>= 1) m = fmaxf(m, __shfl_xor_sync(0xffffffffu, m, o));
    if (lane == 0) red[w] = m;
    __syncthreads();
    m = fmaxf(fmaxf(red[0], red[1]), fmaxf(red[2], red[3]));

    v.x = __expf(v.x - m);
    v.y = __expf(v.y - m);
    v.z = __expf(v.z - m);
    v.w = __expf(v.w - m);
    float s = v.x + v.y + v.z + v.w;
#pragma unroll
    for (int o = 16; o; o >>= 1) s += __shfl_xor_sync(0xffffffffu, s, o);
    if (lane == 0) red[4 + w] = s;
    __syncthreads();
    s = red[4] + red[5] + red[6] + red[7];

    const float inv = __frcp_rn(s);
    v.x *= inv; v.y *= inv; v.z *= inv; v.w *= inv;
    split4_store(v, P + row * 1024 + tid * 4);
}

// ============================================================================
// Host launcher
// ============================================================================
extern "C" void kernel_launch(void* const* d_in, const int* in_sizes, int n_in,
                              void* d_out, int out_size)
{
    (void)in_sizes; (void)n_in; (void)out_size;

    const float* c = (const float*)d_in[0];  // (32,2048,512)
    const float* q = (const float*)d_in[1];  // (32,512,512)
    const float* W = (const float*)d_in[2];  // (512,512) (out,in)
    const float* b = (const float*)d_in[3];  // (512)
    float* out = (float*)d_out;              // (32,2048,512)

    void *pce, *pqe, *pqt, *pwe, *pcf, *pqf, *ppe, *ps;
    cudaGetSymbolAddress(&pce, g_cext);
    cudaGetSymbolAddress(&pqe, g_qext);
    cudaGetSymbolAddress(&pqt, g_qtext);
    cudaGetSymbolAddress(&pwe, g_wext);
    cudaGetSymbolAddress(&pcf, g_cfext);
    cudaGetSymbolAddress(&pqf, g_qfext);
    cudaGetSymbolAddress(&ppe, g_pext);
    cudaGetSymbolAddress(&ps,  g_s);
    __nv_bfloat16* cext  = (__nv_bfloat16*)pce;
    __nv_bfloat16* qext  = (__nv_bfloat16*)pqe;
    __nv_bfloat16* qtext = (__nv_bfloat16*)pqt;
    __nv_bfloat16* wext  = (__nv_bfloat16*)pwe;
    __nv_bfloat16* cfext = (__nv_bfloat16*)pcf;
    __nv_bfloat16* qfext = (__nv_bfloat16*)pqf;
    __nv_bfloat16* pext  = (__nv_bfloat16*)ppe;
    float* sbuf = (float*)ps;

    cudaFuncSetAttribute(gemm_mma<true>,
                         cudaFuncAttributeMaxDynamicSharedMemorySize, GEMM_DSMEM);
    cudaFuncSetAttribute(gemm_mma<false>,
                         cudaFuncAttributeMaxDynamicSharedMemorySize, GEMM_DSMEM);

    // Input splits
    {
        long long n4 = (long long)BATCH * CLEN * DIMD / 4;
        split_ext<<<(unsigned)((n4 + 255) / 256), 256>>>(c, cext, n4);
    }
    {
        long long n4 = (long long)BATCH * QLEN * DIMD / 4;
        split_ext<<<(unsigned)((n4 + 255) / 256), 256>>>(q, qext, n4);
    }
    {
        long long n4 = (long long)DIMD * DIMD / 4;
        split_ext<<<(unsigned)((n4 + 255) / 256), 256>>>(W, wext, n4);
    }
    transpose_split<<<dim3(DIMD / 32, QLEN / 32, BATCH), dim3(32, 8)>>>(q, qtext);

    // 1) c_feat = relu(c @ W^T + b) -> ext   (M=65536, N=512)
    gemm_mma<true><<<dim3(4, 512, 1), 256, GEMM_DSMEM>>>(
        cext, wext, nullptr, cfext, b, 0, 0, 0, 0);
    // 2) q_feat = relu(q @ W^T + b) -> ext   (M=16384, N=512)
    gemm_mma<true><<<dim3(4, 128, 1), 256, GEMM_DSMEM>>>(
        qext, wext, nullptr, qfext, b, 0, 0, 0, 0);
    // 3) S_b = c_feat_b @ q_feat_b^T -> fp32 (per-batch M=2048, N=512)
    gemm_mma<false><<<dim3(4, 16, 32), 256, GEMM_DSMEM>>>(
        cfext, qfext, sbuf, nullptr, nullptr,
        (long long)CLEN, (long long)QLEN, (long long)CLEN * QLEN, QLEN);
    // 4) row softmax -> probs ext
    softmax_ext<<<BATCH * CLEN, 128>>>(sbuf, pext);
    // 5) mix_b = P_b @ q_b -> fp32 out       (per-batch M=2048, N=512)
    gemm_mma<false><<<dim3(4, 16, 32), 256, GEMM_DSMEM>>>(
        pext, qtext, out, nullptr, nullptr,
        (long long)CLEN, (long long)DIMD, (long long)CLEN * DIMD, DIMD);
}

// round 15
// speedup vs baseline: 1.6458x; 1.0268x over previous
#include <cuda_runtime.h>
#include <cuda_bf16.h>
#include <cstdint>

// Problem constants: B=32, c_len=2048, q_len=512, D=512
#define DIMD 512
#define BATCH 32
#define CLEN 2048
#define QLEN 512

typedef unsigned long long u64;

// ============================================================================
// Device scratch (allocation-free). Extended [hi|lo] bf16 planes:
// row-major [rows][1024], hi at cols [0,512), lo at [512,1024).
// ============================================================================
__device__ __nv_bfloat16 g_cext [(size_t)BATCH * CLEN * 1024];   // c     134MB
__device__ __nv_bfloat16 g_qext [(size_t)BATCH * QLEN * 1024];   // q (A)  34MB
__device__ __nv_bfloat16 g_qtext[(size_t)BATCH * DIMD * 1024];   // q^T(B) 34MB
__device__ __nv_bfloat16 g_wext [(size_t)DIMD * 1024];           // W       1MB
__device__ __nv_bfloat16 g_cfext[(size_t)BATCH * CLEN * 1024];   // c_feat 134MB
__device__ __nv_bfloat16 g_qfext[(size_t)BATCH * QLEN * 1024];   // q_feat  34MB
__device__ __nv_bfloat16 g_pext [(size_t)BATCH * CLEN * 1024];   // probs  134MB
__device__ float         g_s    [(size_t)BATCH * CLEN * QLEN];   // scores 128MB

// ============================================================================
// Baseline-PTX helpers (all sm_80+ features; compile on plain sm_103)
// ============================================================================
__device__ __forceinline__ uint32_t smem_to_u32(const void* smem_ptr) {
    uint32_t addr;
    asm("{ .reg .u64 tmp; cvta.to.shared.u64 tmp, %1; cvt.u32.u64 %0, tmp; }"
        : "=r"(addr) : "l"(smem_ptr));
    return addr;
}
__device__ __forceinline__ void ldsm4(uint32_t* r, uint32_t addr) {
    asm volatile("ldmatrix.sync.aligned.m8n8.x4.shared.b16 {%0,%1,%2,%3}, [%4];"
        : "=r"(r[0]), "=r"(r[1]), "=r"(r[2]), "=r"(r[3]) : "r"(addr));
}
__device__ __forceinline__ void mma_bf16(float* d, const uint32_t* a,
                                         uint32_t b0, uint32_t b1) {
    asm volatile(
        "mma.sync.aligned.m16n8k16.row.col.f32.bf16.bf16.f32 "
        "{%0,%1,%2,%3}, {%4,%5,%6,%7}, {%8,%9}, {%0,%1,%2,%3};"
        : "+f"(d[0]), "+f"(d[1]), "+f"(d[2]), "+f"(d[3])
        : "r"(a[0]), "r"(a[1]), "r"(a[2]), "r"(a[3]), "r"(b0), "r"(b1));
}
#define CP_ASYNC16(dst, src) \
    asm volatile("cp.async.cg.shared.global [%0], [%1], 16;" \
        :: "r"(dst), "l"(src) : "memory")
#define CP_COMMIT() asm volatile("cp.async.commit_group;" ::: "memory")
#define CP_WAIT2()  asm volatile("cp.async.wait_group 2;" ::: "memory")

// ---- hi/lo split helpers ----
__device__ __forceinline__ void split2(float x, __nv_bfloat16& h, __nv_bfloat16& l) {
    h = __float2bfloat16_rn(x);
    l = __float2bfloat16_rn(x - __bfloat162float(h));
}
__device__ __forceinline__ void split4_store(float4 v, __nv_bfloat16* dst) {
    __nv_bfloat16 h0, h1, h2, h3, l0, l1, l2, l3;
    split2(v.x, h0, l0); split2(v.y, h1, l1);
    split2(v.z, h2, l2); split2(v.w, h3, l3);
    ushort4 hs, ls;
    hs.x = __bfloat16_as_ushort(h0); hs.y = __bfloat16_as_ushort(h1);
    hs.z = __bfloat16_as_ushort(h2); hs.w = __bfloat16_as_ushort(h3);
    ls.x = __bfloat16_as_ushort(l0); ls.y = __bfloat16_as_ushort(l1);
    ls.z = __bfloat16_as_ushort(l2); ls.w = __bfloat16_as_ushort(l3);
    *(ushort4*)dst = hs;
    *(ushort4*)(dst + 512) = ls;
}
__device__ __forceinline__ void split2_store(float a, float b, __nv_bfloat16* dst) {
    __nv_bfloat16 h0, h1, l0, l1;
    split2(a, h0, l0); split2(b, h1, l1);
    ushort2 hs, ls;
    hs.x = __bfloat16_as_ushort(h0); hs.y = __bfloat16_as_ushort(h1);
    ls.x = __bfloat16_as_ushort(l0); ls.y = __bfloat16_as_ushort(l1);
    *(ushort2*)dst = hs;
    *(ushort2*)(dst + 512) = ls;
}

// ============================================================================
// Split kernels: fp32 [rows][512] -> bf16 ext [rows][1024] (hi|lo)
// ============================================================================
__global__ void split_ext(const float* __restrict__ src,
                          __nv_bfloat16* __restrict__ dst, long long n4)
{
    long long i = (long long)blockIdx.x * blockDim.x + threadIdx.x;
    if (i >= n4) return;
    long long e = i * 4;
    long long row = e >> 9;
    int col = (int)(e & 511);
    float4 v = *(const float4*)(src + e);
    split4_store(v, dst + row * 1024 + col);
}

// q[b][p][d] -> qT_ext[(b*512+d)][p(hi)|512+p(lo)]
__global__ void transpose_split(const float* __restrict__ q,
                                __nv_bfloat16* __restrict__ dst)
{
    __shared__ float t[32][33];
    const int b = blockIdx.z, d0 = blockIdx.x * 32, p0 = blockIdx.y * 32;
    const float* qb = q + ((long long)b * QLEN + p0) * DIMD + d0;
    for (int i = threadIdx.y; i < 32; i += 8)
        t[i][threadIdx.x] = qb[(long long)i * DIMD + threadIdx.x];
    __syncthreads();
    for (int i = threadIdx.y; i < 32; i += 8) {
        float v = t[threadIdx.x][i];
        __nv_bfloat16 h, l;
        split2(v, h, l);
        __nv_bfloat16* dp = dst + ((long long)b * DIMD + d0 + i) * 1024 + p0 + threadIdx.x;
        dp[0] = h;
        dp[512] = l;
    }
}

// ============================================================================
// Split-precision bf16 mma.sync GEMM, 4-stage cp.async pipeline, 2 CTAs/SM.
// D[128,128] = A[128,512]·B[128,512]^T via Ah·Bh + Al·Bh + Ah·Bl, fp32 accum.
// Block: 256 thr = 8 warps (2 M x 4 N), warp tile 64x32, K-chunk 16.
// smem stage: Ah|Al|Bh|Bl planes (4KB each) = 16KB; 4 stages = 64KB.
// EXT=true : C = relu(D + bias) -> bf16 [hi|lo] ext (pitch 1024)
// EXT=false: C = D -> fp32, pitch cPitch
// ============================================================================
#define GSTAGE 16384
#define GEMM_DSMEM (4 * GSTAGE)

// swizzled 16B-chunk offset within a 4KB plane: row 0..127, c 0..1
__device__ __forceinline__ uint32_t swz(int row, int c) {
    return (uint32_t)(row * 32 + ((c ^ ((row >> 2) & 1)) << 4));
}

template <bool EXT>
__global__ void __launch_bounds__(256, 2)
gemm_mma(const __nv_bfloat16* __restrict__ A, const __nv_bfloat16* __restrict__ B,
         float* __restrict__ C, __nv_bfloat16* __restrict__ CE,
         const float* __restrict__ bias,
         long long aZ, long long bZ, long long cZ, int cPitch)
{
    extern __shared__ char dsm[];
    const uint32_t smem0 = smem_to_u32(dsm);

    const int tid = threadIdx.x;
    const int lane = tid & 31;
    const int wid = tid >> 5;
    const int wm = wid & 1;       // 0..1  (M)
    const int wn = wid >> 1;      // 0..3  (N)

    const long long z = blockIdx.z;
    const __nv_bfloat16* Ab = A + (z * aZ + (long long)blockIdx.y * 128) * 1024;
    const __nv_bfloat16* Bb = B + (z * bZ + (long long)blockIdx.x * 128) * 1024;

    // gmem staging role: thread -> (row, 16B chunk)
    const int grow = tid >> 1;          // 0..127
    const int gc   = tid & 1;           // 0..1
    const __nv_bfloat16* gA = Ab + (long long)grow * 1024 + gc * 8;
    const __nv_bfloat16* gB = Bb + (long long)grow * 1024 + gc * 8;
    const uint32_t gsw = swz(grow, gc);

    // ldmatrix addresses (per-lane), offsets within a 4KB plane
    uint32_t offA[4], offB[2];
#pragma unroll
    for (int mf = 0; mf < 4; mf++)
        offA[mf] = swz(wm * 64 + mf * 16 + (lane & 15), lane >> 4);
#pragma unroll
    for (int nf = 0; nf < 2; nf++)
        offB[nf] = swz(wn * 32 + nf * 16 + (lane & 15), lane >> 4);

    float acc[4][4][4];
#pragma unroll
    for (int i = 0; i < 4; i++)
#pragma unroll
        for (int j = 0; j < 4; j++)
#pragma unroll
            for (int k = 0; k < 4; k++) acc[i][j][k] = 0.f;

    // prologue: issue stages 0..2 (one commit group per stage)
#pragma unroll
    for (int s = 0; s < 3; s++) {
        const uint32_t sp = smem0 + s * GSTAGE + gsw;
        const int k0 = s * 16;
        CP_ASYNC16(sp,         (const char*)(gA + k0));
        CP_ASYNC16(sp + 4096,  (const char*)(gA + 512 + k0));
        CP_ASYNC16(sp + 8192,  (const char*)(gB + k0));
        CP_ASYNC16(sp + 12288, (const char*)(gB + 512 + k0));
        CP_COMMIT();
    }

#pragma unroll 1
    for (int kt = 0; kt < 32; kt++) {
        CP_WAIT2();                 // stage kt resident (group accounting below)
        __syncthreads();            // visible to all warps; frees slot (kt-1)&3

        // issue stage kt+3 into slot (kt+3)&3 == (kt-1)&3; commit ALWAYS so
        // groups committed before iter kt's wait == 3+kt  ->  wait_group 2
        // retires exactly through stage kt.
        if (kt + 3 < 32) {
            const uint32_t sp = smem0 + ((kt + 3) & 3) * GSTAGE + gsw;
            const int k0 = (kt + 3) * 16;
            CP_ASYNC16(sp,         (const char*)(gA + k0));
            CP_ASYNC16(sp + 4096,  (const char*)(gA + 512 + k0));
            CP_ASYNC16(sp + 8192,  (const char*)(gB + k0));
            CP_ASYNC16(sp + 12288, (const char*)(gB + 512 + k0));
        }
        CP_COMMIT();

        const uint32_t stage = smem0 + (kt & 3) * GSTAGE;

        // B fragments: [nf16][4 regs]; frag(n0-7)={r0,r2}, frag(n8-15)={r1,r3}
        uint32_t Bh[2][4], Bl[2][4];
#pragma unroll
        for (int nf = 0; nf < 2; nf++) {
            ldsm4(Bh[nf], stage + 8192  + offB[nf]);
            ldsm4(Bl[nf], stage + 12288 + offB[nf]);
        }
#pragma unroll
        for (int mf = 0; mf < 4; mf++) {
            uint32_t Ah[4], Al[4];
            ldsm4(Ah, stage +        offA[mf]);
            ldsm4(Al, stage + 4096 + offA[mf]);
#pragma unroll
            for (int n8 = 0; n8 < 4; n8++) {
                const int nf = n8 >> 1, h = n8 & 1;
                const uint32_t b0h = Bh[nf][h], b1h = Bh[nf][h + 2];
                const uint32_t b0l = Bl[nf][h], b1l = Bl[nf][h + 2];
                mma_bf16(acc[mf][n8], Ah, b0h, b1h);
                mma_bf16(acc[mf][n8], Al, b0h, b1h);
                mma_bf16(acc[mf][n8], Ah, b0l, b1l);
            }
        }
        // no trailing barrier: next iteration's syncthreads protects reuse
    }

    // ---- epilogue: acc -> gmem (fragment layout m16n8 f32) ----
    const int rbase = blockIdx.y * 128 + wm * 64 + (lane >> 2);
    const int cbase = blockIdx.x * 128 + wn * 32 + (lane & 3) * 2;

    if (EXT) {
        __nv_bfloat16* CEb = CE + (z * cZ) * 1024;
#pragma unroll
        for (int mf = 0; mf < 4; mf++) {
#pragma unroll
            for (int n8 = 0; n8 < 4; n8++) {
                const int col = cbase + n8 * 8;
                float b0 = bias ? bias[col]     : 0.f;
                float b1 = bias ? bias[col + 1] : 0.f;
                const float* a = acc[mf][n8];
                const int r0 = rbase + mf * 16;
                float v0 = fmaxf(a[0] + b0, 0.f), v1 = fmaxf(a[1] + b1, 0.f);
                float v2 = fmaxf(a[2] + b0, 0.f), v3 = fmaxf(a[3] + b1, 0.f);
                split2_store(v0, v1, CEb + (long long)r0 * 1024 + col);
                split2_store(v2, v3, CEb + (long long)(r0 + 8) * 1024 + col);
            }
        }
    } else {
        float* Cb = C + z * cZ;
#pragma unroll
        for (int mf = 0; mf < 4; mf++) {
#pragma unroll
            for (int n8 = 0; n8 < 4; n8++) {
                const int col = cbase + n8 * 8;
                const float* a = acc[mf][n8];
                const int r0 = rbase + mf * 16;
                *(float2*)(Cb + (long long)r0 * cPitch + col) =
                    make_float2(a[0], a[1]);
                *(float2*)(Cb + (long long)(r0 + 8) * cPitch + col) =
                    make_float2(a[2], a[3]);
            }
        }
    }
}

// ============================================================================
// Row softmax over 512, fp32 in -> bf16 [hi|lo] ext out. 128 threads/row.
// ============================================================================
__global__ void softmax_ext(const float* __restrict__ S,
                            __nv_bfloat16* __restrict__ P)
{
    __shared__ float red[8];
    const long long row = blockIdx.x;
    const float* p = S + row * (long long)QLEN;
    const int tid = threadIdx.x, lane = tid & 31, w = tid >> 5;

    float4 v = *(const float4*)(p + tid * 4);
    float m = fmaxf(fmaxf(v.x, v.y), fmaxf(v.z, v.w));
#pragma unroll
    for (int o = 16; o; o >>= 1) m = fmaxf(m, __shfl_xor_sync(0xffffffffu, m, o));
    if (lane == 0) red[w] = m;
    __syncthreads();
    m = fmaxf(fmaxf(red[0], red[1]), fmaxf(red[2], red[3]));

    v.x = __expf(v.x - m);
    v.y = __expf(v.y - m);
    v.z = __expf(v.z - m);
    v.w = __expf(v.w - m);
    float s = v.x + v.y + v.z + v.w;
#pragma unroll
    for (int o = 16; o; o >>= 1) s += __shfl_xor_sync(0xffffffffu, s, o);
    if (lane == 0) red[4 + w] = s;
    __syncthreads();
    s = red[4] + red[5] + red[6] + red[7];

    const float inv = __frcp_rn(s);
    v.x *= inv; v.y *= inv; v.z *= inv; v.w *= inv;
    split4_store(v, P + row * 1024 + tid * 4);
}

// ============================================================================
// Host launcher
// ============================================================================
extern "C" void kernel_launch(void* const* d_in, const int* in_sizes, int n_in,
                              void* d_out, int out_size)
{
    (void)in_sizes; (void)n_in; (void)out_size;

    const float* c = (const float*)d_in[0];  // (32,2048,512)
    const float* q = (const float*)d_in[1];  // (32,512,512)
    const float* W = (const float*)d_in[2];  // (512,512) (out,in)
    const float* b = (const float*)d_in[3];  // (512)
    float* out = (float*)d_out;              // (32,2048,512)

    void *pce, *pqe, *pqt, *pwe, *pcf, *pqf, *ppe, *ps;
    cudaGetSymbolAddress(&pce, g_cext);
    cudaGetSymbolAddress(&pqe, g_qext);
    cudaGetSymbolAddress(&pqt, g_qtext);
    cudaGetSymbolAddress(&pwe, g_wext);
    cudaGetSymbolAddress(&pcf, g_cfext);
    cudaGetSymbolAddress(&pqf, g_qfext);
    cudaGetSymbolAddress(&ppe, g_pext);
    cudaGetSymbolAddress(&ps,  g_s);
    __nv_bfloat16* cext  = (__nv_bfloat16*)pce;
    __nv_bfloat16* qext  = (__nv_bfloat16*)pqe;
    __nv_bfloat16* qtext = (__nv_bfloat16*)pqt;
    __nv_bfloat16* wext  = (__nv_bfloat16*)pwe;
    __nv_bfloat16* cfext = (__nv_bfloat16*)pcf;
    __nv_bfloat16* qfext = (__nv_bfloat16*)pqf;
    __nv_bfloat16* pext  = (__nv_bfloat16*)ppe;
    float* sbuf = (float*)ps;

    cudaFuncSetAttribute(gemm_mma<true>,
                         cudaFuncAttributeMaxDynamicSharedMemorySize, GEMM_DSMEM);
    cudaFuncSetAttribute(gemm_mma<false>,
                         cudaFuncAttributeMaxDynamicSharedMemorySize, GEMM_DSMEM);

    // Input splits
    {
        long long n4 = (long long)BATCH * CLEN * DIMD / 4;
        split_ext<<<(unsigned)((n4 + 255) / 256), 256>>>(c, cext, n4);
    }
    {
        long long n4 = (long long)BATCH * QLEN * DIMD / 4;
        split_ext<<<(unsigned)((n4 + 255) / 256), 256>>>(q, qext, n4);
    }
    {
        long long n4 = (long long)DIMD * DIMD / 4;
        split_ext<<<(unsigned)((n4 + 255) / 256), 256>>>(W, wext, n4);
    }
    transpose_split<<<dim3(DIMD / 32, QLEN / 32, BATCH), dim3(32, 8)>>>(q, qtext);

    // 1) c_feat = relu(c @ W^T + b) -> ext   (M=65536, N=512)
    gemm_mma<true><<<dim3(4, 512, 1), 256, GEMM_DSMEM>>>(
        cext, wext, nullptr, cfext, b, 0, 0, 0, 0);
    // 2) q_feat = relu(q @ W^T + b) -> ext   (M=16384, N=512)
    gemm_mma<true><<<dim3(4, 128, 1), 256, GEMM_DSMEM>>>(
        qext, wext, nullptr, qfext, b, 0, 0, 0, 0);
    // 3) S_b = c_feat_b @ q_feat_b^T -> fp32 (per-batch M=2048, N=512)
    gemm_mma<false><<<dim3(4, 16, 32), 256, GEMM_DSMEM>>>(
        cfext, qfext, sbuf, nullptr, nullptr,
        (long long)CLEN, (long long)QLEN, (long long)CLEN * QLEN, QLEN);
    // 4) row softmax -> probs ext
    softmax_ext<<<BATCH * CLEN, 128>>>(sbuf, pext);
    // 5) mix_b = P_b @ q_b -> fp32 out       (per-batch M=2048, N=512)
    gemm_mma<false><<<dim3(4, 16, 32), 256, GEMM_DSMEM>>>(
        pext, qtext, out, nullptr, nullptr,
        (long long)CLEN, (long long)DIMD, (long long)CLEN * DIMD, DIMD);
}

// round 16
// speedup vs baseline: 1.8201x; 1.1058x over previous
#include <cuda_runtime.h>
#include <cuda_bf16.h>
#include <cuda_fp16.h>
#include <cstdint>

// Problem constants: B=32, c_len=2048, q_len=512, D=512
#define DIMD 512
#define BATCH 32
#define CLEN 2048
#define QLEN 512

typedef unsigned long long u64;

// ============================================================================
// Device scratch (allocation-free).
// bf16 ext planes: row-major [rows][1024], hi at cols [0,512), lo [512,1024).
// fp16 planes for the mix GEMM: P single-plane, qT hi/lo ext.
// ============================================================================
__device__ __nv_bfloat16 g_cext [(size_t)BATCH * CLEN * 1024];   // c     134MB
__device__ __nv_bfloat16 g_qext [(size_t)BATCH * QLEN * 1024];   // q (A)  34MB
__device__ __nv_bfloat16 g_wext [(size_t)DIMD * 1024];           // W       1MB
__device__ __nv_bfloat16 g_cfext[(size_t)BATCH * CLEN * 1024];   // c_feat 134MB
__device__ __nv_bfloat16 g_qfext[(size_t)BATCH * QLEN * 1024];   // q_feat  34MB
__device__ float         g_s    [(size_t)BATCH * CLEN * QLEN];   // scores 128MB
__device__ __half        g_pf16 [(size_t)BATCH * CLEN * QLEN];   // probs   64MB
__device__ __half        g_qtf16[(size_t)BATCH * DIMD * 1024];   // q^T ext 34MB

// ============================================================================
// Baseline-PTX helpers (all sm_80+ features; compile on plain sm_103)
// ============================================================================
__device__ __forceinline__ uint32_t smem_to_u32(const void* smem_ptr) {
    uint32_t addr;
    asm("{ .reg .u64 tmp; cvta.to.shared.u64 tmp, %1; cvt.u32.u64 %0, tmp; }"
        : "=r"(addr) : "l"(smem_ptr));
    return addr;
}
__device__ __forceinline__ void ldsm4(uint32_t* r, uint32_t addr) {
    asm volatile("ldmatrix.sync.aligned.m8n8.x4.shared.b16 {%0,%1,%2,%3}, [%4];"
        : "=r"(r[0]), "=r"(r[1]), "=r"(r[2]), "=r"(r[3]) : "r"(addr));
}
__device__ __forceinline__ void mma_bf16(float* d, const uint32_t* a,
                                         uint32_t b0, uint32_t b1) {
    asm volatile(
        "mma.sync.aligned.m16n8k16.row.col.f32.bf16.bf16.f32 "
        "{%0,%1,%2,%3}, {%4,%5,%6,%7}, {%8,%9}, {%0,%1,%2,%3};"
        : "+f"(d[0]), "+f"(d[1]), "+f"(d[2]), "+f"(d[3])
        : "r"(a[0]), "r"(a[1]), "r"(a[2]), "r"(a[3]), "r"(b0), "r"(b1));
}
__device__ __forceinline__ void mma_f16(float* d, const uint32_t* a,
                                        uint32_t b0, uint32_t b1) {
    asm volatile(
        "mma.sync.aligned.m16n8k16.row.col.f32.f16.f16.f32 "
        "{%0,%1,%2,%3}, {%4,%5,%6,%7}, {%8,%9}, {%0,%1,%2,%3};"
        : "+f"(d[0]), "+f"(d[1]), "+f"(d[2]), "+f"(d[3])
        : "r"(a[0]), "r"(a[1]), "r"(a[2]), "r"(a[3]), "r"(b0), "r"(b1));
}
#define CP_ASYNC16(dst, src) \
    asm volatile("cp.async.cg.shared.global [%0], [%1], 16;" \
        :: "r"(dst), "l"(src) : "memory")
#define CP_COMMIT() asm volatile("cp.async.commit_group;" ::: "memory")
#define CP_WAIT2()  asm volatile("cp.async.wait_group 2;" ::: "memory")

// ---- hi/lo split helpers (bf16) ----
__device__ __forceinline__ void split2(float x, __nv_bfloat16& h, __nv_bfloat16& l) {
    h = __float2bfloat16_rn(x);
    l = __float2bfloat16_rn(x - __bfloat162float(h));
}
__device__ __forceinline__ void split4_store(float4 v, __nv_bfloat16* dst) {
    __nv_bfloat16 h0, h1, h2, h3, l0, l1, l2, l3;
    split2(v.x, h0, l0); split2(v.y, h1, l1);
    split2(v.z, h2, l2); split2(v.w, h3, l3);
    ushort4 hs, ls;
    hs.x = __bfloat16_as_ushort(h0); hs.y = __bfloat16_as_ushort(h1);
    hs.z = __bfloat16_as_ushort(h2); hs.w = __bfloat16_as_ushort(h3);
    ls.x = __bfloat16_as_ushort(l0); ls.y = __bfloat16_as_ushort(l1);
    ls.z = __bfloat16_as_ushort(l2); ls.w = __bfloat16_as_ushort(l3);
    *(ushort4*)dst = hs;
    *(ushort4*)(dst + 512) = ls;
}
__device__ __forceinline__ void split2_store(float a, float b, __nv_bfloat16* dst) {
    __nv_bfloat16 h0, h1, l0, l1;
    split2(a, h0, l0); split2(b, h1, l1);
    ushort2 hs, ls;
    hs.x = __bfloat16_as_ushort(h0); hs.y = __bfloat16_as_ushort(h1);
    ls.x = __bfloat16_as_ushort(l0); ls.y = __bfloat16_as_ushort(l1);
    *(ushort2*)dst = hs;
    *(ushort2*)(dst + 512) = ls;
}
// ---- fp16 split ----
__device__ __forceinline__ void split2h(float x, __half& h, __half& l) {
    h = __float2half_rn(x);
    l = __float2half_rn(x - __half2float(h));
}

// ============================================================================
// Split kernels: fp32 [rows][512] -> bf16 ext [rows][1024] (hi|lo)
// ============================================================================
__global__ void split_ext(const float* __restrict__ src,
                          __nv_bfloat16* __restrict__ dst, long long n4)
{
    long long i = (long long)blockIdx.x * blockDim.x + threadIdx.x;
    if (i >= n4) return;
    long long e = i * 4;
    long long row = e >> 9;
    int col = (int)(e & 511);
    float4 v = *(const float4*)(src + e);
    split4_store(v, dst + row * 1024 + col);
}

// q[b][p][d] -> qT_f16[(b*512+d)][p(hi)|512+p(lo)]  (fp16 2-plane, for mix GEMM)
__global__ void transpose_split_f16(const float* __restrict__ q,
                                    __half* __restrict__ dst)
{
    __shared__ float t[32][33];
    const int b = blockIdx.z, d0 = blockIdx.x * 32, p0 = blockIdx.y * 32;
    const float* qb = q + ((long long)b * QLEN + p0) * DIMD + d0;
    for (int i = threadIdx.y; i < 32; i += 8)
        t[i][threadIdx.x] = qb[(long long)i * DIMD + threadIdx.x];
    __syncthreads();
    for (int i = threadIdx.y; i < 32; i += 8) {
        float v = t[threadIdx.x][i];
        __half h, l;
        split2h(v, h, l);
        __half* dp = dst + ((long long)b * DIMD + d0 + i) * 1024 + p0 + threadIdx.x;
        dp[0] = h;
        dp[512] = l;
    }
}

// ============================================================================
// Split-precision bf16 mma.sync GEMM, 4-stage cp.async pipeline, 2 CTAs/SM.
// D[128,128] = A[128,512]·B[128,512]^T via Ah·Bh + Al·Bh + Ah·Bl, fp32 accum.
// Block: 256 thr = 8 warps (2 M x 4 N), warp tile 64x32, K-chunk 16.
// smem stage: Ah|Al|Bh|Bl planes (4KB each) = 16KB; 4 stages = 64KB.
// EXT=true : C = relu(D + bias) -> bf16 [hi|lo] ext (pitch 1024)
// EXT=false: C = D -> fp32, pitch cPitch
// ============================================================================
#define GSTAGE 16384
#define GEMM_DSMEM (4 * GSTAGE)

// swizzled 16B-chunk offset within a 4KB plane: row 0..127, c 0..1
__device__ __forceinline__ uint32_t swz(int row, int c) {
    return (uint32_t)(row * 32 + ((c ^ ((row >> 2) & 1)) << 4));
}

template <bool EXT>
__global__ void __launch_bounds__(256, 2)
gemm_mma(const __nv_bfloat16* __restrict__ A, const __nv_bfloat16* __restrict__ B,
         float* __restrict__ C, __nv_bfloat16* __restrict__ CE,
         const float* __restrict__ bias,
         long long aZ, long long bZ, long long cZ, int cPitch)
{
    extern __shared__ char dsm[];
    const uint32_t smem0 = smem_to_u32(dsm);

    const int tid = threadIdx.x;
    const int lane = tid & 31;
    const int wid = tid >> 5;
    const int wm = wid & 1;       // 0..1  (M)
    const int wn = wid >> 1;      // 0..3  (N)

    const long long z = blockIdx.z;
    const __nv_bfloat16* Ab = A + (z * aZ + (long long)blockIdx.y * 128) * 1024;
    const __nv_bfloat16* Bb = B + (z * bZ + (long long)blockIdx.x * 128) * 1024;

    // gmem staging role: thread -> (row, 16B chunk)
    const int grow = tid >> 1;          // 0..127
    const int gc   = tid & 1;           // 0..1
    const __nv_bfloat16* gA = Ab + (long long)grow * 1024 + gc * 8;
    const __nv_bfloat16* gB = Bb + (long long)grow * 1024 + gc * 8;
    const uint32_t gsw = swz(grow, gc);

    // ldmatrix addresses (per-lane), offsets within a 4KB plane
    uint32_t offA[4], offB[2];
#pragma unroll
    for (int mf = 0; mf < 4; mf++)
        offA[mf] = swz(wm * 64 + mf * 16 + (lane & 15), lane >> 4);
#pragma unroll
    for (int nf = 0; nf < 2; nf++)
        offB[nf] = swz(wn * 32 + nf * 16 + (lane & 15), lane >> 4);

    float acc[4][4][4];
#pragma unroll
    for (int i = 0; i < 4; i++)
#pragma unroll
        for (int j = 0; j < 4; j++)
#pragma unroll
            for (int k = 0; k < 4; k++) acc[i][j][k] = 0.f;

    // prologue: issue stages 0..2 (one commit group per stage)
#pragma unroll
    for (int s = 0; s < 3; s++) {
        const uint32_t sp = smem0 + s * GSTAGE + gsw;
        const int k0 = s * 16;
        CP_ASYNC16(sp,         (const char*)(gA + k0));
        CP_ASYNC16(sp + 4096,  (const char*)(gA + 512 + k0));
        CP_ASYNC16(sp + 8192,  (const char*)(gB + k0));
        CP_ASYNC16(sp + 12288, (const char*)(gB + 512 + k0));
        CP_COMMIT();
    }

#pragma unroll 1
    for (int kt = 0; kt < 32; kt++) {
        CP_WAIT2();                 // stage kt resident (group accounting below)
        __syncthreads();            // visible to all warps; frees slot (kt-1)&3

        // issue stage kt+3 into slot (kt+3)&3 == (kt-1)&3; commit ALWAYS so
        // groups committed before iter kt's wait == 3+kt  ->  wait_group 2
        // retires exactly through stage kt.
        if (kt + 3 < 32) {
            const uint32_t sp = smem0 + ((kt + 3) & 3) * GSTAGE + gsw;
            const int k0 = (kt + 3) * 16;
            CP_ASYNC16(sp,         (const char*)(gA + k0));
            CP_ASYNC16(sp + 4096,  (const char*)(gA + 512 + k0));
            CP_ASYNC16(sp + 8192,  (const char*)(gB + k0));
            CP_ASYNC16(sp + 12288, (const char*)(gB + 512 + k0));
        }
        CP_COMMIT();

        const uint32_t stage = smem0 + (kt & 3) * GSTAGE;

        // B fragments: [nf16][4 regs]; frag(n0-7)={r0,r2}, frag(n8-15)={r1,r3}
        uint32_t Bh[2][4], Bl[2][4];
#pragma unroll
        for (int nf = 0; nf < 2; nf++) {
            ldsm4(Bh[nf], stage + 8192  + offB[nf]);
            ldsm4(Bl[nf], stage + 12288 + offB[nf]);
        }
#pragma unroll
        for (int mf = 0; mf < 4; mf++) {
            uint32_t Ah[4], Al[4];
            ldsm4(Ah, stage +        offA[mf]);
            ldsm4(Al, stage + 4096 + offA[mf]);
#pragma unroll
            for (int n8 = 0; n8 < 4; n8++) {
                const int nf = n8 >> 1, h = n8 & 1;
                const uint32_t b0h = Bh[nf][h], b1h = Bh[nf][h + 2];
                const uint32_t b0l = Bl[nf][h], b1l = Bl[nf][h + 2];
                mma_bf16(acc[mf][n8], Ah, b0h, b1h);
                mma_bf16(acc[mf][n8], Al, b0h, b1h);
                mma_bf16(acc[mf][n8], Ah, b0l, b1l);
            }
        }
        // no trailing barrier: next iteration's syncthreads protects reuse
    }

    // ---- epilogue: acc -> gmem (fragment layout m16n8 f32) ----
    const int rbase = blockIdx.y * 128 + wm * 64 + (lane >> 2);
    const int cbase = blockIdx.x * 128 + wn * 32 + (lane & 3) * 2;

    if (EXT) {
        __nv_bfloat16* CEb = CE + (z * cZ) * 1024;
#pragma unroll
        for (int mf = 0; mf < 4; mf++) {
#pragma unroll
            for (int n8 = 0; n8 < 4; n8++) {
                const int col = cbase + n8 * 8;
                float b0 = bias ? bias[col]     : 0.f;
                float b1 = bias ? bias[col + 1] : 0.f;
                const float* a = acc[mf][n8];
                const int r0 = rbase + mf * 16;
                float v0 = fmaxf(a[0] + b0, 0.f), v1 = fmaxf(a[1] + b1, 0.f);
                float v2 = fmaxf(a[2] + b0, 0.f), v3 = fmaxf(a[3] + b1, 0.f);
                split2_store(v0, v1, CEb + (long long)r0 * 1024 + col);
                split2_store(v2, v3, CEb + (long long)(r0 + 8) * 1024 + col);
            }
        }
    } else {
        float* Cb = C + z * cZ;
#pragma unroll
        for (int mf = 0; mf < 4; mf++) {
#pragma unroll
            for (int n8 = 0; n8 < 4; n8++) {
                const int col = cbase + n8 * 8;
                const float* a = acc[mf][n8];
                const int r0 = rbase + mf * 16;
                *(float2*)(Cb + (long long)r0 * cPitch + col) =
                    make_float2(a[0], a[1]);
                *(float2*)(Cb + (long long)(r0 + 8) * cPitch + col) =
                    make_float2(a[2], a[3]);
            }
        }
    }
}

// ============================================================================
// Mix GEMM (fp16, 2 terms): out[128,128] = P[128,512] · qT[128,512]^T
// P: fp16 single plane (pitch 512). qT: fp16 ext hi|lo (pitch 1024).
// Terms: Ph·qh + Ph·ql. 2/3 the MMA count of the bf16 path.
// Stage: Ap|Bh|Bl planes (4KB each) = 12KB; 4 stages = 48KB. 2 CTAs/SM.
// ============================================================================
#define MSTAGE 12288
#define MIX_DSMEM (4 * MSTAGE)

__global__ void __launch_bounds__(256, 2)
gemm_mix(const __half* __restrict__ A, const __half* __restrict__ B,
         float* __restrict__ C)
{
    extern __shared__ char dsm[];
    const uint32_t smem0 = smem_to_u32(dsm);

    const int tid = threadIdx.x;
    const int lane = tid & 31;
    const int wid = tid >> 5;
    const int wm = wid & 1;
    const int wn = wid >> 1;

    const long long z = blockIdx.z;
    const __half* Ab = A + z * ((long long)CLEN * 512)
                         + (long long)blockIdx.y * 128 * 512;
    const __half* Bb = B + z * ((long long)DIMD * 1024)
                         + (long long)blockIdx.x * 128 * 1024;

    const int grow = tid >> 1;
    const int gc   = tid & 1;
    const __half* gA = Ab + (long long)grow * 512 + gc * 8;
    const __half* gB = Bb + (long long)grow * 1024 + gc * 8;
    const uint32_t gsw = swz(grow, gc);

    uint32_t offA[4], offB[2];
#pragma unroll
    for (int mf = 0; mf < 4; mf++)
        offA[mf] = swz(wm * 64 + mf * 16 + (lane & 15), lane >> 4);
#pragma unroll
    for (int nf = 0; nf < 2; nf++)
        offB[nf] = swz(wn * 32 + nf * 16 + (lane & 15), lane >> 4);

    float acc[4][4][4];
#pragma unroll
    for (int i = 0; i < 4; i++)
#pragma unroll
        for (int j = 0; j < 4; j++)
#pragma unroll
            for (int k = 0; k < 4; k++) acc[i][j][k] = 0.f;

#pragma unroll
    for (int s = 0; s < 3; s++) {
        const uint32_t sp = smem0 + s * MSTAGE + gsw;
        const int k0 = s * 16;
        CP_ASYNC16(sp,        (const char*)(gA + k0));
        CP_ASYNC16(sp + 4096, (const char*)(gB + k0));
        CP_ASYNC16(sp + 8192, (const char*)(gB + 512 + k0));
        CP_COMMIT();
    }

#pragma unroll 1
    for (int kt = 0; kt < 32; kt++) {
        CP_WAIT2();
        __syncthreads();

        if (kt + 3 < 32) {
            const uint32_t sp = smem0 + ((kt + 3) & 3) * MSTAGE + gsw;
            const int k0 = (kt + 3) * 16;
            CP_ASYNC16(sp,        (const char*)(gA + k0));
            CP_ASYNC16(sp + 4096, (const char*)(gB + k0));
            CP_ASYNC16(sp + 8192, (const char*)(gB + 512 + k0));
        }
        CP_COMMIT();

        const uint32_t stage = smem0 + (kt & 3) * MSTAGE;

        uint32_t Bh[2][4], Bl[2][4];
#pragma unroll
        for (int nf = 0; nf < 2; nf++) {
            ldsm4(Bh[nf], stage + 4096 + offB[nf]);
            ldsm4(Bl[nf], stage + 8192 + offB[nf]);
        }
#pragma unroll
        for (int mf = 0; mf < 4; mf++) {
            uint32_t Ap[4];
            ldsm4(Ap, stage + offA[mf]);
#pragma unroll
            for (int n8 = 0; n8 < 4; n8++) {
                const int nf = n8 >> 1, h = n8 & 1;
                mma_f16(acc[mf][n8], Ap, Bh[nf][h], Bh[nf][h + 2]);
                mma_f16(acc[mf][n8], Ap, Bl[nf][h], Bl[nf][h + 2]);
            }
        }
    }

    const int rbase = blockIdx.y * 128 + wm * 64 + (lane >> 2);
    const int cbase = blockIdx.x * 128 + wn * 32 + (lane & 3) * 2;
    float* Cb = C + z * ((long long)CLEN * DIMD);
#pragma unroll
    for (int mf = 0; mf < 4; mf++) {
#pragma unroll
        for (int n8 = 0; n8 < 4; n8++) {
            const int col = cbase + n8 * 8;
            const float* a = acc[mf][n8];
            const int r0 = rbase + mf * 16;
            *(float2*)(Cb + (long long)r0 * DIMD + col) = make_float2(a[0], a[1]);
            *(float2*)(Cb + (long long)(r0 + 8) * DIMD + col) = make_float2(a[2], a[3]);
        }
    }
}

// ============================================================================
// Row softmax over 512, fp32 in -> fp16 single plane out. 128 threads/row.
// ============================================================================
__global__ void softmax_f16(const float* __restrict__ S,
                            __half* __restrict__ P)
{
    __shared__ float red[8];
    const long long row = blockIdx.x;
    const float* p = S + row * (long long)QLEN;
    const int tid = threadIdx.x, lane = tid & 31, w = tid >> 5;

    float4 v = *(const float4*)(p + tid * 4);
    float m = fmaxf(fmaxf(v.x, v.y), fmaxf(v.z, v.w));
#pragma unroll
    for (int o = 16; o; o >>= 1) m = fmaxf(m, __shfl_xor_sync(0xffffffffu, m, o));
    if (lane == 0) red[w] = m;
    __syncthreads();
    m = fmaxf(fmaxf(red[0], red[1]), fmaxf(red[2], red[3]));

    v.x = __expf(v.x - m);
    v.y = __expf(v.y - m);
    v.z = __expf(v.z - m);
    v.w = __expf(v.w - m);
    float s = v.x + v.y + v.z + v.w;
#pragma unroll
    for (int o = 16; o; o >>= 1) s += __shfl_xor_sync(0xffffffffu, s, o);
    if (lane == 0) red[4 + w] = s;
    __syncthreads();
    s = red[4] + red[5] + red[6] + red[7];

    const float inv = __frcp_rn(s);
    ushort4 o4;
    o4.x = __half_as_ushort(__float2half_rn(v.x * inv));
    o4.y = __half_as_ushort(__float2half_rn(v.y * inv));
    o4.z = __half_as_ushort(__float2half_rn(v.z * inv));
    o4.w = __half_as_ushort(__float2half_rn(v.w * inv));
    *(ushort4*)(P + row * QLEN + tid * 4) = o4;
}

// ============================================================================
// Host launcher
// ============================================================================
extern "C" void kernel_launch(void* const* d_in, const int* in_sizes, int n_in,
                              void* d_out, int out_size)
{
    (void)in_sizes; (void)n_in; (void)out_size;

    const float* c = (const float*)d_in[0];  // (32,2048,512)
    const float* q = (const float*)d_in[1];  // (32,512,512)
    const float* W = (const float*)d_in[2];  // (512,512) (out,in)
    const float* b = (const float*)d_in[3];  // (512)
    float* out = (float*)d_out;              // (32,2048,512)

    void *pce, *pqe, *pwe, *pcf, *pqf, *ps, *ppf, *pqt;
    cudaGetSymbolAddress(&pce, g_cext);
    cudaGetSymbolAddress(&pqe, g_qext);
    cudaGetSymbolAddress(&pwe, g_wext);
    cudaGetSymbolAddress(&pcf, g_cfext);
    cudaGetSymbolAddress(&pqf, g_qfext);
    cudaGetSymbolAddress(&ps,  g_s);
    cudaGetSymbolAddress(&ppf, g_pf16);
    cudaGetSymbolAddress(&pqt, g_qtf16);
    __nv_bfloat16* cext  = (__nv_bfloat16*)pce;
    __nv_bfloat16* qext  = (__nv_bfloat16*)pqe;
    __nv_bfloat16* wext  = (__nv_bfloat16*)pwe;
    __nv_bfloat16* cfext = (__nv_bfloat16*)pcf;
    __nv_bfloat16* qfext = (__nv_bfloat16*)pqf;
    float*  sbuf  = (float*)ps;
    __half* pf16  = (__half*)ppf;
    __half* qtf16 = (__half*)pqt;

    cudaFuncSetAttribute(gemm_mma<true>,
                         cudaFuncAttributeMaxDynamicSharedMemorySize, GEMM_DSMEM);
    cudaFuncSetAttribute(gemm_mma<false>,
                         cudaFuncAttributeMaxDynamicSharedMemorySize, GEMM_DSMEM);
    cudaFuncSetAttribute(gemm_mix,
                         cudaFuncAttributeMaxDynamicSharedMemorySize, MIX_DSMEM);

    // Input splits
    {
        long long n4 = (long long)BATCH * CLEN * DIMD / 4;
        split_ext<<<(unsigned)((n4 + 255) / 256), 256>>>(c, cext, n4);
    }
    {
        long long n4 = (long long)BATCH * QLEN * DIMD / 4;
        split_ext<<<(unsigned)((n4 + 255) / 256), 256>>>(q, qext, n4);
    }
    {
        long long n4 = (long long)DIMD * DIMD / 4;
        split_ext<<<(unsigned)((n4 + 255) / 256), 256>>>(W, wext, n4);
    }
    transpose_split_f16<<<dim3(DIMD / 32, QLEN / 32, BATCH), dim3(32, 8)>>>(q, qtf16);

    // 1) c_feat = relu(c @ W^T + b) -> ext   (M=65536, N=512)
    gemm_mma<true><<<dim3(4, 512, 1), 256, GEMM_DSMEM>>>(
        cext, wext, nullptr, cfext, b, 0, 0, 0, 0);
    // 2) q_feat = relu(q @ W^T + b) -> ext   (M=16384, N=512)
    gemm_mma<true><<<dim3(4, 128, 1), 256, GEMM_DSMEM>>>(
        qext, wext, nullptr, qfext, b, 0, 0, 0, 0);
    // 3) S_b = c_feat_b @ q_feat_b^T -> fp32 (per-batch M=2048, N=512)
    gemm_mma<false><<<dim3(4, 16, 32), 256, GEMM_DSMEM>>>(
        cfext, qfext, sbuf, nullptr, nullptr,
        (long long)CLEN, (long long)QLEN, (long long)CLEN * QLEN, QLEN);
    // 4) row softmax -> probs fp16 (single plane)
    softmax_f16<<<BATCH * CLEN, 128>>>(sbuf, pf16);
    // 5) mix_b = P_b @ q_b -> fp32 out       (fp16 2-term, per-batch)
    gemm_mix<<<dim3(4, 16, 32), 256, MIX_DSMEM>>>(pf16, qtf16, out);
}

// round 17
// speedup vs baseline: 1.9761x; 1.0857x over previous
#include <cuda_runtime.h>
#include <cuda_bf16.h>
#include <cuda_fp16.h>
#include <cstdint>

// Problem constants: B=32, c_len=2048, q_len=512, D=512
#define DIMD 512
#define BATCH 32
#define CLEN 2048
#define QLEN 512

typedef unsigned long long u64;

// ============================================================================
// Device scratch (allocation-free).
// bf16 ext planes: row-major [rows][1024], hi at cols [0,512), lo [512,1024).
// fp16 planes for the mix GEMM: P single-plane, qT single-plane.
// ============================================================================
__device__ __nv_bfloat16 g_cext [(size_t)BATCH * CLEN * 1024];   // c     134MB
__device__ __nv_bfloat16 g_qext [(size_t)BATCH * QLEN * 1024];   // q (A)  34MB
__device__ __nv_bfloat16 g_wext [(size_t)DIMD * 1024];           // W       1MB
__device__ __nv_bfloat16 g_cfext[(size_t)BATCH * CLEN * 1024];   // c_feat 134MB
__device__ __nv_bfloat16 g_qfext[(size_t)BATCH * QLEN * 1024];   // q_feat  34MB
__device__ float         g_s    [(size_t)BATCH * CLEN * QLEN];   // scores 128MB
__device__ __half        g_pf16 [(size_t)BATCH * CLEN * QLEN];   // probs   64MB
__device__ __half        g_qtf16[(size_t)BATCH * DIMD * 512];    // q^T     17MB

// ============================================================================
// Baseline-PTX helpers (all sm_80+ features; compile on plain sm_103)
// ============================================================================
__device__ __forceinline__ uint32_t smem_to_u32(const void* smem_ptr) {
    uint32_t addr;
    asm("{ .reg .u64 tmp; cvta.to.shared.u64 tmp, %1; cvt.u32.u64 %0, tmp; }"
        : "=r"(addr) : "l"(smem_ptr));
    return addr;
}
__device__ __forceinline__ void ldsm4(uint32_t* r, uint32_t addr) {
    asm volatile("ldmatrix.sync.aligned.m8n8.x4.shared.b16 {%0,%1,%2,%3}, [%4];"
        : "=r"(r[0]), "=r"(r[1]), "=r"(r[2]), "=r"(r[3]) : "r"(addr));
}
__device__ __forceinline__ void mma_bf16(float* d, const uint32_t* a,
                                         uint32_t b0, uint32_t b1) {
    asm volatile(
        "mma.sync.aligned.m16n8k16.row.col.f32.bf16.bf16.f32 "
        "{%0,%1,%2,%3}, {%4,%5,%6,%7}, {%8,%9}, {%0,%1,%2,%3};"
        : "+f"(d[0]), "+f"(d[1]), "+f"(d[2]), "+f"(d[3])
        : "r"(a[0]), "r"(a[1]), "r"(a[2]), "r"(a[3]), "r"(b0), "r"(b1));
}
__device__ __forceinline__ void mma_f16(float* d, const uint32_t* a,
                                        uint32_t b0, uint32_t b1) {
    asm volatile(
        "mma.sync.aligned.m16n8k16.row.col.f32.f16.f16.f32 "
        "{%0,%1,%2,%3}, {%4,%5,%6,%7}, {%8,%9}, {%0,%1,%2,%3};"
        : "+f"(d[0]), "+f"(d[1]), "+f"(d[2]), "+f"(d[3])
        : "r"(a[0]), "r"(a[1]), "r"(a[2]), "r"(a[3]), "r"(b0), "r"(b1));
}
#define CP_ASYNC16(dst, src) \
    asm volatile("cp.async.cg.shared.global [%0], [%1], 16;" \
        :: "r"(dst), "l"(src) : "memory")
#define CP_COMMIT() asm volatile("cp.async.commit_group;" ::: "memory")
#define CP_WAIT2()  asm volatile("cp.async.wait_group 2;" ::: "memory")

// ---- hi/lo split helpers (bf16) ----
__device__ __forceinline__ void split2(float x, __nv_bfloat16& h, __nv_bfloat16& l) {
    h = __float2bfloat16_rn(x);
    l = __float2bfloat16_rn(x - __bfloat162float(h));
}
__device__ __forceinline__ void split4_store(float4 v, __nv_bfloat16* dst) {
    __nv_bfloat16 h0, h1, h2, h3, l0, l1, l2, l3;
    split2(v.x, h0, l0); split2(v.y, h1, l1);
    split2(v.z, h2, l2); split2(v.w, h3, l3);
    ushort4 hs, ls;
    hs.x = __bfloat16_as_ushort(h0); hs.y = __bfloat16_as_ushort(h1);
    hs.z = __bfloat16_as_ushort(h2); hs.w = __bfloat16_as_ushort(h3);
    ls.x = __bfloat16_as_ushort(l0); ls.y = __bfloat16_as_ushort(l1);
    ls.z = __bfloat16_as_ushort(l2); ls.w = __bfloat16_as_ushort(l3);
    *(ushort4*)dst = hs;
    *(ushort4*)(dst + 512) = ls;
}
__device__ __forceinline__ void split2_store(float a, float b, __nv_bfloat16* dst) {
    __nv_bfloat16 h0, h1, l0, l1;
    split2(a, h0, l0); split2(b, h1, l1);
    ushort2 hs, ls;
    hs.x = __bfloat16_as_ushort(h0); hs.y = __bfloat16_as_ushort(h1);
    ls.x = __bfloat16_as_ushort(l0); ls.y = __bfloat16_as_ushort(l1);
    *(ushort2*)dst = hs;
    *(ushort2*)(dst + 512) = ls;
}

// ============================================================================
// Split kernels: fp32 [rows][512] -> bf16 ext [rows][1024] (hi|lo)
// ============================================================================
__global__ void split_ext(const float* __restrict__ src,
                          __nv_bfloat16* __restrict__ dst, long long n4)
{
    long long i = (long long)blockIdx.x * blockDim.x + threadIdx.x;
    if (i >= n4) return;
    long long e = i * 4;
    long long row = e >> 9;
    int col = (int)(e & 511);
    float4 v = *(const float4*)(src + e);
    split4_store(v, dst + row * 1024 + col);
}

// q[b][p][d] -> qT_f16[(b*512+d)][p]  (single fp16 plane, pitch 512)
__global__ void transpose_f16(const float* __restrict__ q,
                              __half* __restrict__ dst)
{
    __shared__ float t[32][33];
    const int b = blockIdx.z, d0 = blockIdx.x * 32, p0 = blockIdx.y * 32;
    const float* qb = q + ((long long)b * QLEN + p0) * DIMD + d0;
    for (int i = threadIdx.y; i < 32; i += 8)
        t[i][threadIdx.x] = qb[(long long)i * DIMD + threadIdx.x];
    __syncthreads();
    for (int i = threadIdx.y; i < 32; i += 8) {
        dst[((long long)b * DIMD + d0 + i) * 512 + p0 + threadIdx.x] =
            __float2half_rn(t[threadIdx.x][i]);
    }
}

// ============================================================================
// Split-precision bf16 mma.sync GEMM, 4-stage cp.async pipeline, 2 CTAs/SM.
// D[128,128] = A[128,512]·B[128,512]^T via Ah·Bh + Al·Bh + Ah·Bl, fp32 accum.
// Block: 256 thr = 8 warps (2 M x 4 N), warp tile 64x32, K-chunk 16.
// smem stage: Ah|Al|Bh|Bl planes (4KB each) = 16KB; 4 stages = 64KB.
// EXT=true : C = relu(D + bias) -> bf16 [hi|lo] ext (pitch 1024)
// EXT=false: C = D -> fp32, pitch cPitch
// ============================================================================
#define GSTAGE 16384
#define GEMM_DSMEM (4 * GSTAGE)

// swizzled 16B-chunk offset within a 4KB plane: row 0..127, c 0..1
__device__ __forceinline__ uint32_t swz(int row, int c) {
    return (uint32_t)(row * 32 + ((c ^ ((row >> 2) & 1)) << 4));
}

template <bool EXT>
__global__ void __launch_bounds__(256, 2)
gemm_mma(const __nv_bfloat16* __restrict__ A, const __nv_bfloat16* __restrict__ B,
         float* __restrict__ C, __nv_bfloat16* __restrict__ CE,
         const float* __restrict__ bias,
         long long aZ, long long bZ, long long cZ, int cPitch)
{
    extern __shared__ char dsm[];
    const uint32_t smem0 = smem_to_u32(dsm);

    const int tid = threadIdx.x;
    const int lane = tid & 31;
    const int wid = tid >> 5;
    const int wm = wid & 1;       // 0..1  (M)
    const int wn = wid >> 1;      // 0..3  (N)

    const long long z = blockIdx.z;
    const __nv_bfloat16* Ab = A + (z * aZ + (long long)blockIdx.y * 128) * 1024;
    const __nv_bfloat16* Bb = B + (z * bZ + (long long)blockIdx.x * 128) * 1024;

    // gmem staging role: thread -> (row, 16B chunk)
    const int grow = tid >> 1;          // 0..127
    const int gc   = tid & 1;           // 0..1
    const __nv_bfloat16* gA = Ab + (long long)grow * 1024 + gc * 8;
    const __nv_bfloat16* gB = Bb + (long long)grow * 1024 + gc * 8;
    const uint32_t gsw = swz(grow, gc);

    // ldmatrix addresses (per-lane), offsets within a 4KB plane
    uint32_t offA[4], offB[2];
#pragma unroll
    for (int mf = 0; mf < 4; mf++)
        offA[mf] = swz(wm * 64 + mf * 16 + (lane & 15), lane >> 4);
#pragma unroll
    for (int nf = 0; nf < 2; nf++)
        offB[nf] = swz(wn * 32 + nf * 16 + (lane & 15), lane >> 4);

    float acc[4][4][4];
#pragma unroll
    for (int i = 0; i < 4; i++)
#pragma unroll
        for (int j = 0; j < 4; j++)
#pragma unroll
            for (int k = 0; k < 4; k++) acc[i][j][k] = 0.f;

    // prologue: issue stages 0..2 (one commit group per stage)
#pragma unroll
    for (int s = 0; s < 3; s++) {
        const uint32_t sp = smem0 + s * GSTAGE + gsw;
        const int k0 = s * 16;
        CP_ASYNC16(sp,         (const char*)(gA + k0));
        CP_ASYNC16(sp + 4096,  (const char*)(gA + 512 + k0));
        CP_ASYNC16(sp + 8192,  (const char*)(gB + k0));
        CP_ASYNC16(sp + 12288, (const char*)(gB + 512 + k0));
        CP_COMMIT();
    }

#pragma unroll 1
    for (int kt = 0; kt < 32; kt++) {
        CP_WAIT2();                 // stage kt resident (group accounting below)
        __syncthreads();            // visible to all warps; frees slot (kt-1)&3

        // issue stage kt+3 into slot (kt+3)&3 == (kt-1)&3; commit ALWAYS so
        // groups committed before iter kt's wait == 3+kt  ->  wait_group 2
        // retires exactly through stage kt.
        if (kt + 3 < 32) {
            const uint32_t sp = smem0 + ((kt + 3) & 3) * GSTAGE + gsw;
            const int k0 = (kt + 3) * 16;
            CP_ASYNC16(sp,         (const char*)(gA + k0));
            CP_ASYNC16(sp + 4096,  (const char*)(gA + 512 + k0));
            CP_ASYNC16(sp + 8192,  (const char*)(gB + k0));
            CP_ASYNC16(sp + 12288, (const char*)(gB + 512 + k0));
        }
        CP_COMMIT();

        const uint32_t stage = smem0 + (kt & 3) * GSTAGE;

        // B fragments: [nf16][4 regs]; frag(n0-7)={r0,r2}, frag(n8-15)={r1,r3}
        uint32_t Bh[2][4], Bl[2][4];
#pragma unroll
        for (int nf = 0; nf < 2; nf++) {
            ldsm4(Bh[nf], stage + 8192  + offB[nf]);
            ldsm4(Bl[nf], stage + 12288 + offB[nf]);
        }
#pragma unroll
        for (int mf = 0; mf < 4; mf++) {
            uint32_t Ah[4], Al[4];
            ldsm4(Ah, stage +        offA[mf]);
            ldsm4(Al, stage + 4096 + offA[mf]);
#pragma unroll
            for (int n8 = 0; n8 < 4; n8++) {
                const int nf = n8 >> 1, h = n8 & 1;
                const uint32_t b0h = Bh[nf][h], b1h = Bh[nf][h + 2];
                const uint32_t b0l = Bl[nf][h], b1l = Bl[nf][h + 2];
                mma_bf16(acc[mf][n8], Ah, b0h, b1h);
                mma_bf16(acc[mf][n8], Al, b0h, b1h);
                mma_bf16(acc[mf][n8], Ah, b0l, b1l);
            }
        }
        // no trailing barrier: next iteration's syncthreads protects reuse
    }

    // ---- epilogue: acc -> gmem (fragment layout m16n8 f32) ----
    const int rbase = blockIdx.y * 128 + wm * 64 + (lane >> 2);
    const int cbase = blockIdx.x * 128 + wn * 32 + (lane & 3) * 2;

    if (EXT) {
        __nv_bfloat16* CEb = CE + (z * cZ) * 1024;
#pragma unroll
        for (int mf = 0; mf < 4; mf++) {
#pragma unroll
            for (int n8 = 0; n8 < 4; n8++) {
                const int col = cbase + n8 * 8;
                float b0 = bias ? bias[col]     : 0.f;
                float b1 = bias ? bias[col + 1] : 0.f;
                const float* a = acc[mf][n8];
                const int r0 = rbase + mf * 16;
                float v0 = fmaxf(a[0] + b0, 0.f), v1 = fmaxf(a[1] + b1, 0.f);
                float v2 = fmaxf(a[2] + b0, 0.f), v3 = fmaxf(a[3] + b1, 0.f);
                split2_store(v0, v1, CEb + (long long)r0 * 1024 + col);
                split2_store(v2, v3, CEb + (long long)(r0 + 8) * 1024 + col);
            }
        }
    } else {
        float* Cb = C + z * cZ;
#pragma unroll
        for (int mf = 0; mf < 4; mf++) {
#pragma unroll
            for (int n8 = 0; n8 < 4; n8++) {
                const int col = cbase + n8 * 8;
                const float* a = acc[mf][n8];
                const int r0 = rbase + mf * 16;
                *(float2*)(Cb + (long long)r0 * cPitch + col) =
                    make_float2(a[0], a[1]);
                *(float2*)(Cb + (long long)(r0 + 8) * cPitch + col) =
                    make_float2(a[2], a[3]);
            }
        }
    }
}

// ============================================================================
// Mix GEMM (fp16, 1 term): out[128,128] = P[128,512] · qT[128,512]^T
// P: fp16 single plane (pitch 512). qT: fp16 single plane (pitch 512).
// Stage: Ap|Bp planes (4KB each) = 8KB; 4 stages = 32KB. 2 CTAs/SM.
// ============================================================================
#define MSTAGE 8192
#define MIX_DSMEM (4 * MSTAGE)

__global__ void __launch_bounds__(256, 2)
gemm_mix(const __half* __restrict__ A, const __half* __restrict__ B,
         float* __restrict__ C)
{
    extern __shared__ char dsm[];
    const uint32_t smem0 = smem_to_u32(dsm);

    const int tid = threadIdx.x;
    const int lane = tid & 31;
    const int wid = tid >> 5;
    const int wm = wid & 1;
    const int wn = wid >> 1;

    const long long z = blockIdx.z;
    const __half* Ab = A + z * ((long long)CLEN * 512)
                         + (long long)blockIdx.y * 128 * 512;
    const __half* Bb = B + z * ((long long)DIMD * 512)
                         + (long long)blockIdx.x * 128 * 512;

    const int grow = tid >> 1;
    const int gc   = tid & 1;
    const __half* gA = Ab + (long long)grow * 512 + gc * 8;
    const __half* gB = Bb + (long long)grow * 512 + gc * 8;
    const uint32_t gsw = swz(grow, gc);

    uint32_t offA[4], offB[2];
#pragma unroll
    for (int mf = 0; mf < 4; mf++)
        offA[mf] = swz(wm * 64 + mf * 16 + (lane & 15), lane >> 4);
#pragma unroll
    for (int nf = 0; nf < 2; nf++)
        offB[nf] = swz(wn * 32 + nf * 16 + (lane & 15), lane >> 4);

    float acc[4][4][4];
#pragma unroll
    for (int i = 0; i < 4; i++)
#pragma unroll
        for (int j = 0; j < 4; j++)
#pragma unroll
            for (int k = 0; k < 4; k++) acc[i][j][k] = 0.f;

#pragma unroll
    for (int s = 0; s < 3; s++) {
        const uint32_t sp = smem0 + s * MSTAGE + gsw;
        const int k0 = s * 16;
        CP_ASYNC16(sp,        (const char*)(gA + k0));
        CP_ASYNC16(sp + 4096, (const char*)(gB + k0));
        CP_COMMIT();
    }

#pragma unroll 1
    for (int kt = 0; kt < 32; kt++) {
        CP_WAIT2();
        __syncthreads();

        if (kt + 3 < 32) {
            const uint32_t sp = smem0 + ((kt + 3) & 3) * MSTAGE + gsw;
            const int k0 = (kt + 3) * 16;
            CP_ASYNC16(sp,        (const char*)(gA + k0));
            CP_ASYNC16(sp + 4096, (const char*)(gB + k0));
        }
        CP_COMMIT();

        const uint32_t stage = smem0 + (kt & 3) * MSTAGE;

        uint32_t Bp[2][4];
#pragma unroll
        for (int nf = 0; nf < 2; nf++)
            ldsm4(Bp[nf], stage + 4096 + offB[nf]);
#pragma unroll
        for (int mf = 0; mf < 4; mf++) {
            uint32_t Ap[4];
            ldsm4(Ap, stage + offA[mf]);
#pragma unroll
            for (int n8 = 0; n8 < 4; n8++) {
                const int nf = n8 >> 1, h = n8 & 1;
                mma_f16(acc[mf][n8], Ap, Bp[nf][h], Bp[nf][h + 2]);
            }
        }
    }

    const int rbase = blockIdx.y * 128 + wm * 64 + (lane >> 2);
    const int cbase = blockIdx.x * 128 + wn * 32 + (lane & 3) * 2;
    float* Cb = C + z * ((long long)CLEN * DIMD);
#pragma unroll
    for (int mf = 0; mf < 4; mf++) {
#pragma unroll
        for (int n8 = 0; n8 < 4; n8++) {
            const int col = cbase + n8 * 8;
            const float* a = acc[mf][n8];
            const int r0 = rbase + mf * 16;
            *(float2*)(Cb + (long long)r0 * DIMD + col) = make_float2(a[0], a[1]);
            *(float2*)(Cb + (long long)(r0 + 8) * DIMD + col) = make_float2(a[2], a[3]);
        }
    }
}

// ============================================================================
// Row softmax over 512, fp32 in -> fp16 single plane out. 128 threads/row.
// ============================================================================
__global__ void softmax_f16(const float* __restrict__ S,
                            __half* __restrict__ P)
{
    __shared__ float red[8];
    const long long row = blockIdx.x;
    const float* p = S + row * (long long)QLEN;
    const int tid = threadIdx.x, lane = tid & 31, w = tid >> 5;

    float4 v = *(const float4*)(p + tid * 4);
    float m = fmaxf(fmaxf(v.x, v.y), fmaxf(v.z, v.w));
#pragma unroll
    for (int o = 16; o; o >>= 1) m = fmaxf(m, __shfl_xor_sync(0xffffffffu, m, o));
    if (lane == 0) red[w] = m;
    __syncthreads();
    m = fmaxf(fmaxf(red[0], red[1]), fmaxf(red[2], red[3]));

    v.x = __expf(v.x - m);
    v.y = __expf(v.y - m);
    v.z = __expf(v.z - m);
    v.w = __expf(v.w - m);
    float s = v.x + v.y + v.z + v.w;
#pragma unroll
    for (int o = 16; o; o >>= 1) s += __shfl_xor_sync(0xffffffffu, s, o);
    if (lane == 0) red[4 + w] = s;
    __syncthreads();
    s = red[4] + red[5] + red[6] + red[7];

    const float inv = __frcp_rn(s);
    ushort4 o4;
    o4.x = __half_as_ushort(__float2half_rn(v.x * inv));
    o4.y = __half_as_ushort(__float2half_rn(v.y * inv));
    o4.z = __half_as_ushort(__float2half_rn(v.z * inv));
    o4.w = __half_as_ushort(__float2half_rn(v.w * inv));
    *(ushort4*)(P + row * QLEN + tid * 4) = o4;
}

// ============================================================================
// Host launcher
// ============================================================================
extern "C" void kernel_launch(void* const* d_in, const int* in_sizes, int n_in,
                              void* d_out, int out_size)
{
    (void)in_sizes; (void)n_in; (void)out_size;

    const float* c = (const float*)d_in[0];  // (32,2048,512)
    const float* q = (const float*)d_in[1];  // (32,512,512)
    const float* W = (const float*)d_in[2];  // (512,512) (out,in)
    const float* b = (const float*)d_in[3];  // (512)
    float* out = (float*)d_out;              // (32,2048,512)

    void *pce, *pqe, *pwe, *pcf, *pqf, *ps, *ppf, *pqt;
    cudaGetSymbolAddress(&pce, g_cext);
    cudaGetSymbolAddress(&pqe, g_qext);
    cudaGetSymbolAddress(&pwe, g_wext);
    cudaGetSymbolAddress(&pcf, g_cfext);
    cudaGetSymbolAddress(&pqf, g_qfext);
    cudaGetSymbolAddress(&ps,  g_s);
    cudaGetSymbolAddress(&ppf, g_pf16);
    cudaGetSymbolAddress(&pqt, g_qtf16);
    __nv_bfloat16* cext  = (__nv_bfloat16*)pce;
    __nv_bfloat16* qext  = (__nv_bfloat16*)pqe;
    __nv_bfloat16* wext  = (__nv_bfloat16*)pwe;
    __nv_bfloat16* cfext = (__nv_bfloat16*)pcf;
    __nv_bfloat16* qfext = (__nv_bfloat16*)pqf;
    float*  sbuf  = (float*)ps;
    __half* pf16  = (__half*)ppf;
    __half* qtf16 = (__half*)pqt;

    cudaFuncSetAttribute(gemm_mma<true>,
                         cudaFuncAttributeMaxDynamicSharedMemorySize, GEMM_DSMEM);
    cudaFuncSetAttribute(gemm_mma<false>,
                         cudaFuncAttributeMaxDynamicSharedMemorySize, GEMM_DSMEM);
    cudaFuncSetAttribute(gemm_mix,
                         cudaFuncAttributeMaxDynamicSharedMemorySize, MIX_DSMEM);

    // Input splits
    {
        long long n4 = (long long)BATCH * CLEN * DIMD / 4;
        split_ext<<<(unsigned)((n4 + 255) / 256), 256>>>(c, cext, n4);
    }
    {
        long long n4 = (long long)BATCH * QLEN * DIMD / 4;
        split_ext<<<(unsigned)((n4 + 255) / 256), 256>>>(q, qext, n4);
    }
    {
        long long n4 = (long long)DIMD * DIMD / 4;
        split_ext<<<(unsigned)((n4 + 255) / 256), 256>>>(W, wext, n4);
    }
    transpose_f16<<<dim3(DIMD / 32, QLEN / 32, BATCH), dim3(32, 8)>>>(q, qtf16);

    // 1) c_feat = relu(c @ W^T + b) -> ext   (M=65536, N=512)
    gemm_mma<true><<<dim3(4, 512, 1), 256, GEMM_DSMEM>>>(
        cext, wext, nullptr, cfext, b, 0, 0, 0, 0);
    // 2) q_feat = relu(q @ W^T + b) -> ext   (M=16384, N=512)
    gemm_mma<true><<<dim3(4, 128, 1), 256, GEMM_DSMEM>>>(
        qext, wext, nullptr, qfext, b, 0, 0, 0, 0);
    // 3) S_b = c_feat_b @ q_feat_b^T -> fp32 (per-batch M=2048, N=512)
    gemm_mma<false><<<dim3(4, 16, 32), 256, GEMM_DSMEM>>>(
        cfext, qfext, sbuf, nullptr, nullptr,
        (long long)CLEN, (long long)QLEN, (long long)CLEN * QLEN, QLEN);
    // 4) row softmax -> probs fp16 (single plane)
    softmax_f16<<<BATCH * CLEN, 128>>>(sbuf, pf16);
    // 5) mix_b = P_b @ q_b -> fp32 out       (fp16 1-term, per-batch)
    gemm_mix<<<dim3(4, 16, 32), 256, MIX_DSMEM>>>(pf16, qtf16, out);
}